// round 6
// baseline (speedup 1.0000x reference)
#include <cuda_runtime.h>
#include <cuda_bf16.h>
#include <math.h>
#include <stdint.h>

#define B     64
#define NSUB  4
#define PP    128
#define TP    512
#define DD    256
#define HH    256
#define FEAT  131072
#define M1    128
#define NROWS (B*TP)            // 32768
#define KCHUNKS 256             // split-K chunks for mlp1 (512 K each)

#define STRA  20                // mlp1 A-tile stride
#define STRB  136               // mlp1 B-tile stride
#define STRW  264               // k_layer B-tile stride (256 + 8)

// k_layer dynamic smem layout (words):
//   S1h: [0, 16384)   S1l: [16384, 32768)   stage: [32768, 49664)
#define SMEM_LAYER_WORDS 49664
// phase1 stage offsets within stage base: A: st*3072 (hi 0,lo 1536); X: 6144+st*4224 (hi 0, lo 2112)
// phase2 stage: W: st*8448 (hi 0, lo 4224)

// ---------------- scratch (device globals; no allocation) ----------------
__device__ float    g_invn[B*TP];
__device__ float    g_dinv[B*TP];
__device__ float    g_rs[B*TP];                    // dinv[r] * rowsum(A')
__device__ uint32_t g_Xh[(size_t)NROWS*128];       // x rowK split (for simA)
__device__ uint32_t g_Xl[(size_t)NROWS*128];
__device__ uint32_t g_Xch[(size_t)(NROWS/2)*256];  // x colpair split (layer1 phase-1 B)
__device__ uint32_t g_Xcl[(size_t)(NROWS/2)*256];
__device__ uint32_t g_Aph[(size_t)256*PP*64];      // A' = A*dinv_c, kpair packed
__device__ uint32_t g_Apl[(size_t)256*PP*64];
__device__ uint32_t g_W1h[128*256], g_W1l[128*256];
__device__ uint32_t g_W2h[128*256], g_W2l[128*256];
__device__ uint32_t g_Hrh[(size_t)NROWS*128];      // raw (pre-BN) H split rowK
__device__ uint32_t g_Hrl[(size_t)NROWS*128];
__device__ uint32_t g_Hch[(size_t)(NROWS/2)*256];  // postBN H1 colpair (layer2 phase-1 B)
__device__ uint32_t g_Hcl[(size_t)(NROWS/2)*256];
__device__ uint32_t g_Hbh[(size_t)NROWS*128];      // postBN H2 rowK (mlp1 A)
__device__ uint32_t g_Hbl[(size_t)NROWS*128];
__device__ float    g_sum1[HH], g_sumsq1[HH], g_sum2[HH], g_sumsq2[HH];
__device__ float    g_Z1part[(size_t)KCHUNKS*B*M1];
__device__ float    g_z1[B*M1];

// ---------------- helpers ----------------
__device__ __forceinline__ void split2(float a, float b, uint32_t& h, uint32_t& l) {
    __nv_bfloat162 hb = __floats2bfloat162_rn(a, b);
    float2 hf = __bfloat1622float2(hb);
    __nv_bfloat162 lb = __floats2bfloat162_rn(a - hf.x, b - hf.y);
    h = *(uint32_t*)&hb;
    l = *(uint32_t*)&lb;
}
// reconstruct two fp32 from hi/lo bf16x2 words
__device__ __forceinline__ void unsplit2(uint32_t h, uint32_t l, float& a, float& b) {
    float2 hf = __bfloat1622float2(*(__nv_bfloat162*)&h);
    float2 lf = __bfloat1622float2(*(__nv_bfloat162*)&l);
    a = hf.x + lf.x;
    b = hf.y + lf.y;
}
__device__ __forceinline__ void mma16(float* c, const uint32_t* a, const uint32_t* b) {
    asm volatile("mma.sync.aligned.m16n8k16.row.col.f32.bf16.bf16.f32 "
                 "{%0,%1,%2,%3}, {%4,%5,%6,%7}, {%8,%9}, {%0,%1,%2,%3};\n"
                 : "+f"(c[0]), "+f"(c[1]), "+f"(c[2]), "+f"(c[3])
                 : "r"(a[0]), "r"(a[1]), "r"(a[2]), "r"(a[3]),
                   "r"(b[0]), "r"(b[1]));
}
__device__ __forceinline__ void cpa(uint32_t* dst, const void* src) {
    uint32_t d = (uint32_t)__cvta_generic_to_shared(dst);
    asm volatile("cp.async.cg.shared.global [%0], [%1], 16;" :: "r"(d), "l"(src));
}
#define CP_COMMIT() asm volatile("cp.async.commit_group;")
#define CP_WAIT0()  asm volatile("cp.async.wait_group 0;")

// ---------------- 1/||x_row|| + zero BN accumulators ----------------
__global__ void k_invn(const float* __restrict__ x) {
    if (blockIdx.x == 0 && threadIdx.x < 256) {
        g_sum1[threadIdx.x] = 0.f; g_sumsq1[threadIdx.x] = 0.f;
        g_sum2[threadIdx.x] = 0.f; g_sumsq2[threadIdx.x] = 0.f;
    }
    int row  = blockIdx.x * 8 + (threadIdx.x >> 5);
    int lane = threadIdx.x & 31;
    const float* xr = x + (size_t)row * DD;
    float s = 0.f;
#pragma unroll
    for (int i = 0; i < 8; i++) { float v = xr[lane + 32*i]; s += v*v; }
#pragma unroll
    for (int o = 16; o; o >>= 1) s += __shfl_xor_sync(0xffffffffu, s, o);
    if (lane == 0) g_invn[row] = 1.0f / fmaxf(sqrtf(s), 1e-12f);
}

// ---------------- split x -> rowK (g_Xh/l) AND colpair (g_Xch/l) ----------------
__global__ void k_splitX(const float* __restrict__ x) {
    int idx = blockIdx.x * 256 + threadIdx.x;      // (NROWS/2)*(DD/4) tasks
    int i = idx >> 6, q = (idx & 63) * 4;          // row-pair i, col q
    int r0 = 2*i, r1 = 2*i + 1;
    float4 a = *(const float4*)(x + (size_t)r0*DD + q);
    float4 b = *(const float4*)(x + (size_t)r1*DD + q);
    uint32_t h, l;
    // rowK for r0, r1
    uint2 H0, L0, H1, L1;
    split2(a.x, a.y, H0.x, L0.x); split2(a.z, a.w, H0.y, L0.y);
    split2(b.x, b.y, H1.x, L1.x); split2(b.z, b.w, H1.y, L1.y);
    *(uint2*)&g_Xh[(size_t)r0*128 + (q>>1)] = H0;
    *(uint2*)&g_Xl[(size_t)r0*128 + (q>>1)] = L0;
    *(uint2*)&g_Xh[(size_t)r1*128 + (q>>1)] = H1;
    *(uint2*)&g_Xl[(size_t)r1*128 + (q>>1)] = L1;
    // colpair
    uint4 CH, CL;
    split2(a.x, b.x, CH.x, CL.x);
    split2(a.y, b.y, CH.y, CL.y);
    split2(a.z, b.z, CH.z, CL.z);
    split2(a.w, b.w, CH.w, CL.w);
    *(uint4*)&g_Xch[(size_t)i*256 + q] = CH;
    *(uint4*)&g_Xcl[(size_t)i*256 + q] = CL;
    (void)h; (void)l;
}

// ---------------- split W1/W2 -> kpairN packed (one launch) ----------------
__global__ void k_splitW(const float* __restrict__ W1, const float* __restrict__ W2) {
    int blk = blockIdx.x;
    const float* W = (blk < 32) ? W1 : W2;
    uint32_t* Wh = (blk < 32) ? g_W1h : g_W2h;
    uint32_t* Wl = (blk < 32) ? g_W1l : g_W2l;
    int idx = (blk & 31) * 256 + threadIdx.x;
    int kp = idx >> 6, c = (idx & 63) * 4;
    float4 a = *(const float4*)&W[(2*kp)*256 + c];
    float4 b = *(const float4*)&W[(2*kp+1)*256 + c];
    uint4 H, L;
    split2(a.x, b.x, H.x, L.x);
    split2(a.y, b.y, H.y, L.y);
    split2(a.z, b.z, H.z, L.z);
    split2(a.w, b.w, H.w, L.w);
    *(uint4*)&Wh[kp*256 + c] = H;
    *(uint4*)&Wl[kp*256 + c] = L;
}

// ---------------- per-(b,n): A' = ((cos+1)/2*mask, diag 1)*dinv_c; dinv; rs ----------------
__global__ void __launch_bounds__(256) k_simA(const float* __restrict__ mask) {
    __shared__ uint32_t S[10240];
    __shared__ float sInv[128];
    __shared__ float sdeg[128];
    __shared__ float sDv[128];
    __shared__ float sRs[128];
    int bn = blockIdx.x;
    int b = bn >> 2, n = bn & 3;
    int rowbase = b*TP + n*PP;
    int tid = threadIdx.x, w = tid >> 5, lane = tid & 31, g = lane >> 2, t = lane & 3;
    int wm = w & 3, wn = w >> 2;
    if (tid < 128) { sInv[tid] = g_invn[rowbase + tid]; sdeg[tid] = 0.f; sRs[tid] = 0.f; }

    float acc[2][8][4];
#pragma unroll
    for (int mi=0;mi<2;mi++)
#pragma unroll
        for (int ni=0;ni<8;ni++)
#pragma unroll
            for (int q=0;q<4;q++) acc[mi][ni][q] = 0.f;

    {
        int kc = 0;
#pragma unroll
        for (int it = 0; it < 2; it++) {
            int idx = tid + it*256;
            int r = idx >> 2, q = (idx & 3) * 4;
            cpa(&S[r*STRA + q],        g_Xh + (size_t)(rowbase + r)*128 + kc*16 + q);
            cpa(&S[2560 + r*STRA + q], g_Xl + (size_t)(rowbase + r)*128 + kc*16 + q);
        }
        CP_COMMIT();
    }
    for (int it = 0; it < 8; it++) {
        CP_WAIT0();
        __syncthreads();
        if (it + 1 < 8) {
            int st = (it+1) & 1, kc = it+1;
#pragma unroll
            for (int i2 = 0; i2 < 2; i2++) {
                int idx = tid + i2*256;
                int r = idx >> 2, q = (idx & 3) * 4;
                cpa(&S[st*5120 + r*STRA + q],        g_Xh + (size_t)(rowbase + r)*128 + kc*16 + q);
                cpa(&S[st*5120 + 2560 + r*STRA + q], g_Xl + (size_t)(rowbase + r)*128 + kc*16 + q);
            }
            CP_COMMIT();
        }
        const uint32_t* H = S + (it&1)*5120;
        const uint32_t* L = H + 2560;
#pragma unroll
        for (int kb = 0; kb < 16; kb += 8) {
            uint32_t ah[2][4], al[2][4];
#pragma unroll
            for (int mi=0;mi<2;mi++) {
                int rb = wm*32 + mi*16;
                ah[mi][0] = H[(rb+g  )*STRA + kb+t  ]; al[mi][0] = L[(rb+g  )*STRA + kb+t  ];
                ah[mi][1] = H[(rb+g+8)*STRA + kb+t  ]; al[mi][1] = L[(rb+g+8)*STRA + kb+t  ];
                ah[mi][2] = H[(rb+g  )*STRA + kb+t+4]; al[mi][2] = L[(rb+g  )*STRA + kb+t+4];
                ah[mi][3] = H[(rb+g+8)*STRA + kb+t+4]; al[mi][3] = L[(rb+g+8)*STRA + kb+t+4];
            }
#pragma unroll
            for (int ni=0;ni<8;ni++) {
                int cb = wn*64 + ni*8 + g;
                uint32_t bh[2], bl[2];
                bh[0] = H[cb*STRA + kb+t];   bl[0] = L[cb*STRA + kb+t];
                bh[1] = H[cb*STRA + kb+t+4]; bl[1] = L[cb*STRA + kb+t+4];
#pragma unroll
                for (int mi=0;mi<2;mi++) {
                    mma16(acc[mi][ni], ah[mi], bh);
                    mma16(acc[mi][ni], ah[mi], bl);
                    mma16(acc[mi][ni], al[mi], bh);
                }
            }
        }
    }
    __syncthreads();

    // pass 1: degrees
#pragma unroll
    for (int ni=0;ni<8;ni++) {
        int c0 = wn*64 + ni*8 + 2*t, c1 = c0 + 1;
        float ic0 = sInv[c0], ic1 = sInv[c1];
#pragma unroll
        for (int mi=0;mi<2;mi++) {
            int r0 = wm*32 + mi*16 + g, r1 = r0 + 8;
            float i0 = sInv[r0], i1 = sInv[r1];
            float v00 = (r0==c0) ? 1.f : (acc[mi][ni][0]*i0*ic0 + 1.f)*0.5f*mask[r0*PP+c0];
            float v01 = (r0==c1) ? 1.f : (acc[mi][ni][1]*i0*ic1 + 1.f)*0.5f*mask[r0*PP+c1];
            float v10 = (r1==c0) ? 1.f : (acc[mi][ni][2]*i1*ic0 + 1.f)*0.5f*mask[r1*PP+c0];
            float v11 = (r1==c1) ? 1.f : (acc[mi][ni][3]*i1*ic1 + 1.f)*0.5f*mask[r1*PP+c1];
            atomicAdd(&sdeg[r0], v00 + v01);
            atomicAdd(&sdeg[r1], v10 + v11);
        }
    }
    __syncthreads();
    if (tid < 128) {
        float deg = sdeg[tid];
        sDv[tid] = (deg > 0.f) ? rsqrtf(fmaxf(deg, 1e-12f)) : 0.f;
    }
    __syncthreads();

    // pass 2: A' = v * dinv_c, write split, accumulate rowsum(A')
#pragma unroll
    for (int ni=0;ni<8;ni++) {
        int c0 = wn*64 + ni*8 + 2*t, c1 = c0 + 1;
        int cp = c0 >> 1;
        float ic0 = sInv[c0], ic1 = sInv[c1];
        float d0 = sDv[c0], d1 = sDv[c1];
#pragma unroll
        for (int mi=0;mi<2;mi++) {
            int r0 = wm*32 + mi*16 + g, r1 = r0 + 8;
            float i0 = sInv[r0], i1 = sInv[r1];
            float v00 = (r0==c0) ? 1.f : (acc[mi][ni][0]*i0*ic0 + 1.f)*0.5f*mask[r0*PP+c0];
            float v01 = (r0==c1) ? 1.f : (acc[mi][ni][1]*i0*ic1 + 1.f)*0.5f*mask[r0*PP+c1];
            float v10 = (r1==c0) ? 1.f : (acc[mi][ni][2]*i1*ic0 + 1.f)*0.5f*mask[r1*PP+c0];
            float v11 = (r1==c1) ? 1.f : (acc[mi][ni][3]*i1*ic1 + 1.f)*0.5f*mask[r1*PP+c1];
            float a00 = v00*d0, a01 = v01*d1, a10 = v10*d0, a11 = v11*d1;
            uint32_t h, l;
            split2(a00, a01, h, l);
            g_Aph[((size_t)bn*128 + r0)*64 + cp] = h;
            g_Apl[((size_t)bn*128 + r0)*64 + cp] = l;
            split2(a10, a11, h, l);
            g_Aph[((size_t)bn*128 + r1)*64 + cp] = h;
            g_Apl[((size_t)bn*128 + r1)*64 + cp] = l;
            atomicAdd(&sRs[r0], a00 + a01);
            atomicAdd(&sRs[r1], a10 + a11);
        }
    }
    __syncthreads();
    if (tid < 128) {
        g_dinv[rowbase + tid] = sDv[tid];
        g_rs[rowbase + tid]   = sDv[tid] * sRs[tid];
    }
}

// ---------------- fused layer: H_raw = Dr*(A' @ Xc @ W) + rs*b^T, BN stats ----------------
__global__ void __launch_bounds__(512, 1) k_layer(const uint32_t* __restrict__ Xch,
                                                  const uint32_t* __restrict__ Xcl,
                                                  const uint32_t* __restrict__ Wh,
                                                  const uint32_t* __restrict__ Wl,
                                                  const float* __restrict__ bias,
                                                  float* __restrict__ sumArr,
                                                  float* __restrict__ sqArr) {
    extern __shared__ uint32_t S[];   // SMEM_LAYER_WORDS
    uint32_t* S1h = S;                // 16384
    uint32_t* S1l = S + 16384;        // 16384
    uint32_t* STG = S + 32768;        // 16896
    __shared__ float sDv[128], sRsv[128], sBias[256];
    __shared__ float sSum[256], sSq[256];

    int bn = blockIdx.x;
    int rowbase = bn * 128;
    int tid = threadIdx.x, w = tid >> 5, lane = tid & 31, g = lane >> 2, t = lane & 3;
    int wm = w & 3, wn = w >> 2;          // 4 x 4 warps: 32-row x 64-col tiles
    if (tid < 128) { sDv[tid] = g_dinv[rowbase + tid]; sRsv[tid] = g_rs[rowbase + tid]; }
    if (tid < 256) { sBias[tid] = bias[tid]; sSum[tid] = 0.f; sSq[tid] = 0.f; }

    float acc[2][8][4];
#pragma unroll
    for (int mi=0;mi<2;mi++)
#pragma unroll
        for (int ni=0;ni<8;ni++)
#pragma unroll
            for (int q=0;q<4;q++) acc[mi][ni][q] = 0.f;

    // ================= phase 1: S1 = A' @ Xc  (M=128,N=256,K=128; 8 chunks of 16) ======
    {
        int c = 0, st = 0;
        {   // A': 128 rows x 8 words, hi+lo
            int half = tid >> 8;
            int r = (tid & 255) >> 1, q = (tid & 1) * 4;
            const uint32_t* src = (half ? g_Apl : g_Aph) + ((size_t)bn*128 + r)*64 + c*8 + q;
            cpa(&STG[st*3072 + half*1536 + r*12 + q], src);
        }
#pragma unroll
        for (int half = 0; half < 2; half++) {
            int kp = tid >> 6, cc = (tid & 63) * 4;
            const uint32_t* src = (half ? Xcl : Xch) + ((size_t)(bn*64 + c*8 + kp))*256 + cc;
            cpa(&STG[6144 + st*4224 + half*2112 + kp*STRW + cc], src);
        }
        CP_COMMIT();
    }
    for (int it = 0; it < 8; it++) {
        CP_WAIT0();
        __syncthreads();
        if (it + 1 < 8) {
            int c = it + 1, st = c & 1;
            {
                int half = tid >> 8;
                int r = (tid & 255) >> 1, q = (tid & 1) * 4;
                const uint32_t* src = (half ? g_Apl : g_Aph) + ((size_t)bn*128 + r)*64 + c*8 + q;
                cpa(&STG[st*3072 + half*1536 + r*12 + q], src);
            }
#pragma unroll
            for (int half = 0; half < 2; half++) {
                int kp = tid >> 6, cc = (tid & 63) * 4;
                const uint32_t* src = (half ? Xcl : Xch) + ((size_t)(bn*64 + c*8 + kp))*256 + cc;
                cpa(&STG[6144 + st*4224 + half*2112 + kp*STRW + cc], src);
            }
            CP_COMMIT();
        }
        const uint32_t* AH = STG + (it&1)*3072;
        const uint32_t* AL = AH + 1536;
        const uint32_t* BH = STG + 6144 + (it&1)*4224;
        const uint32_t* BL = BH + 2112;
        uint32_t ah[2][4], al[2][4];
#pragma unroll
        for (int mi=0;mi<2;mi++) {
            int rb = wm*32 + mi*16;
            ah[mi][0] = AH[(rb+g  )*12 + t  ]; al[mi][0] = AL[(rb+g  )*12 + t  ];
            ah[mi][1] = AH[(rb+g+8)*12 + t  ]; al[mi][1] = AL[(rb+g+8)*12 + t  ];
            ah[mi][2] = AH[(rb+g  )*12 + t+4]; al[mi][2] = AL[(rb+g  )*12 + t+4];
            ah[mi][3] = AH[(rb+g+8)*12 + t+4]; al[mi][3] = AL[(rb+g+8)*12 + t+4];
        }
#pragma unroll
        for (int ni=0;ni<8;ni++) {
            int cb = wn*64 + ni*8 + g;
            uint32_t bh[2], bl[2];
            bh[0] = BH[t*STRW + cb];     bl[0] = BL[t*STRW + cb];
            bh[1] = BH[(t+4)*STRW + cb]; bl[1] = BL[(t+4)*STRW + cb];
#pragma unroll
            for (int mi=0;mi<2;mi++) {
                mma16(acc[mi][ni], ah[mi], bh);
                mma16(acc[mi][ni], ah[mi], bl);
                mma16(acc[mi][ni], al[mi], bh);
            }
        }
    }
    __syncthreads();
    // write S1 split to smem (swizzled: word ^ (4*(r&7)))
#pragma unroll
    for (int mi=0;mi<2;mi++) {
        int r0 = wm*32 + mi*16 + g, r1 = r0 + 8;
        int sw0 = (r0 & 7) << 2, sw1 = (r1 & 7) << 2;
#pragma unroll
        for (int ni=0;ni<8;ni++) {
            int cp = wn*32 + ni*4 + t;
            uint32_t h, l;
            split2(acc[mi][ni][0], acc[mi][ni][1], h, l);
            S1h[r0*128 + (cp ^ sw0)] = h; S1l[r0*128 + (cp ^ sw0)] = l;
            split2(acc[mi][ni][2], acc[mi][ni][3], h, l);
            S1h[r1*128 + (cp ^ sw1)] = h; S1l[r1*128 + (cp ^ sw1)] = l;
        }
    }
#pragma unroll
    for (int mi=0;mi<2;mi++)
#pragma unroll
        for (int ni=0;ni<8;ni++)
#pragma unroll
            for (int q=0;q<4;q++) acc[mi][ni][q] = 0.f;
    __syncthreads();

    // ================= phase 2: H = S1 @ W  (M=128,N=256,K=256; 8 chunks of 32) ========
    {
        int c = 0, st = 0;
#pragma unroll
        for (int i2 = 0; i2 < 2; i2++) {
            int idx = tid + i2*512;
            int kp = idx >> 6, cc = (idx & 63) * 4;
            cpa(&STG[st*8448 + kp*STRW + cc],        Wh + (size_t)(c*16 + kp)*256 + cc);
            cpa(&STG[st*8448 + 4224 + kp*STRW + cc], Wl + (size_t)(c*16 + kp)*256 + cc);
        }
        CP_COMMIT();
    }
    for (int it = 0; it < 8; it++) {
        CP_WAIT0();
        __syncthreads();
        if (it + 1 < 8) {
            int c = it + 1, st = c & 1;
#pragma unroll
            for (int i2 = 0; i2 < 2; i2++) {
                int idx = tid + i2*512;
                int kp = idx >> 6, cc = (idx & 63) * 4;
                cpa(&STG[st*8448 + kp*STRW + cc],        Wh + (size_t)(c*16 + kp)*256 + cc);
                cpa(&STG[st*8448 + 4224 + kp*STRW + cc], Wl + (size_t)(c*16 + kp)*256 + cc);
            }
            CP_COMMIT();
        }
        const uint32_t* BH = STG + (it&1)*8448;
        const uint32_t* BL = BH + 4224;
#pragma unroll
        for (int kb = 0; kb < 16; kb += 8) {
            uint32_t ah[2][4], al[2][4];
#pragma unroll
            for (int mi=0;mi<2;mi++) {
                int rb = wm*32 + mi*16;
                int r0 = rb + g, r1 = r0 + 8;
                int sw = g << 2;   // (r&7)==g for both rows
                int w0 = (it*16 + kb + t) ^ sw, w1 = (it*16 + kb + t + 4) ^ sw;
                ah[mi][0] = S1h[r0*128 + w0]; al[mi][0] = S1l[r0*128 + w0];
                ah[mi][1] = S1h[r1*128 + w0]; al[mi][1] = S1l[r1*128 + w0];
                ah[mi][2] = S1h[r0*128 + w1]; al[mi][2] = S1l[r0*128 + w1];
                ah[mi][3] = S1h[r1*128 + w1]; al[mi][3] = S1l[r1*128 + w1];
            }
#pragma unroll
            for (int ni=0;ni<8;ni++) {
                int cb = wn*64 + ni*8 + g;
                uint32_t bh[2], bl[2];
                bh[0] = BH[(kb+t  )*STRW + cb]; bl[0] = BL[(kb+t  )*STRW + cb];
                bh[1] = BH[(kb+t+4)*STRW + cb]; bl[1] = BL[(kb+t+4)*STRW + cb];
#pragma unroll
                for (int mi=0;mi<2;mi++) {
                    mma16(acc[mi][ni], ah[mi], bh);
                    mma16(acc[mi][ni], ah[mi], bl);
                    mma16(acc[mi][ni], al[mi], bh);
                }
            }
        }
    }
    // epilogue: H = dinv[r]*acc + rs[r]*bias[c]; stats; write raw split rowK
#pragma unroll
    for (int ni=0;ni<8;ni++) {
        int c0 = wn*64 + ni*8 + 2*t, c1 = c0 + 1;
        int cp = c0 >> 1;
        float b0 = sBias[c0], b1 = sBias[c1];
        float cs0 = 0.f, cs1 = 0.f, cq0 = 0.f, cq1 = 0.f;
#pragma unroll
        for (int mi=0;mi<2;mi++) {
            int r0 = wm*32 + mi*16 + g, r1 = r0 + 8;
            float d0 = sDv[r0], d1 = sDv[r1];
            float rs0 = sRsv[r0], rs1 = sRsv[r1];
            float v00 = fmaf(d0, acc[mi][ni][0], rs0*b0);
            float v01 = fmaf(d0, acc[mi][ni][1], rs0*b1);
            float v10 = fmaf(d1, acc[mi][ni][2], rs1*b0);
            float v11 = fmaf(d1, acc[mi][ni][3], rs1*b1);
            uint32_t h, l;
            split2(v00, v01, h, l);
            g_Hrh[(size_t)(rowbase + r0)*128 + cp] = h;
            g_Hrl[(size_t)(rowbase + r0)*128 + cp] = l;
            split2(v10, v11, h, l);
            g_Hrh[(size_t)(rowbase + r1)*128 + cp] = h;
            g_Hrl[(size_t)(rowbase + r1)*128 + cp] = l;
            cs0 += v00 + v10; cs1 += v01 + v11;
            cq0 += v00*v00 + v10*v10; cq1 += v01*v01 + v11*v11;
        }
        atomicAdd(&sSum[c0], cs0);
        atomicAdd(&sSum[c1], cs1);
        atomicAdd(&sSq[c0],  cq0);
        atomicAdd(&sSq[c1],  cq1);
    }
    __syncthreads();
    if (tid < 256) {
        atomicAdd(&sumArr[tid], sSum[tid]);
        atomicAdd(&sqArr[tid],  sSq[tid]);
    }
}

// ---------------- bnpass1: raw rowK -> postBN colpair (for layer-2 phase 1) ----------------
__global__ void __launch_bounds__(256) k_bnpass1(const float* __restrict__ gam,
                                                 const float* __restrict__ bet) {
    __shared__ float sSc[256], sSh[256];
    {
        int c = threadIdx.x;
        const float invn = 1.0f / (float)NROWS;
        float m = g_sum1[c] * invn;
        float v = g_sumsq1[c] * invn - m*m;
        float sc = gam[c] * rsqrtf(v + 1e-5f);
        sSc[c] = sc; sSh[c] = bet[c] - m*sc;
    }
    __syncthreads();
    int bn = blockIdx.x;
    int rowbase = bn * 128;
    for (int iter = 0; iter < 32; iter++) {
        int task = iter * 256 + threadIdx.x;     // 8192 tasks: (i=0..63) x (hp=0..127)
        int i = task >> 7, hp = task & 127;
        int r0 = rowbase + 2*i, r1 = r0 + 1;
        uint32_t wh0 = g_Hrh[(size_t)r0*128 + hp], wl0 = g_Hrl[(size_t)r0*128 + hp];
        uint32_t wh1 = g_Hrh[(size_t)r1*128 + hp], wl1 = g_Hrl[(size_t)r1*128 + hp];
        float e00, e01, e10, e11;
        unsplit2(wh0, wl0, e00, e01);
        unsplit2(wh1, wl1, e10, e11);
        int c0 = 2*hp, c1 = c0 + 1;
        e00 = fmaxf(fmaf(e00, sSc[c0], sSh[c0]), 0.f);
        e01 = fmaxf(fmaf(e01, sSc[c1], sSh[c1]), 0.f);
        e10 = fmaxf(fmaf(e10, sSc[c0], sSh[c0]), 0.f);
        e11 = fmaxf(fmaf(e11, sSc[c1], sSh[c1]), 0.f);
        uint2 H, L;
        split2(e00, e10, H.x, L.x);    // h = c0: {row r0, row r1}
        split2(e01, e11, H.y, L.y);    // h = c1
        *(uint2*)&g_Hch[(size_t)(bn*64 + i)*256 + c0] = H;
        *(uint2*)&g_Hcl[(size_t)(bn*64 + i)*256 + c0] = L;
    }
}

// ---------------- bnpass2: raw rowK -> postBN rowK (for mlp1) ----------------
__global__ void k_bnpass2(const float* __restrict__ gam, const float* __restrict__ bet) {
    __shared__ float sSc[256], sSh[256];
    {
        int c = threadIdx.x;
        const float invn = 1.0f / (float)NROWS;
        float m = g_sum2[c] * invn;
        float v = g_sumsq2[c] * invn - m*m;
        float sc = gam[c] * rsqrtf(v + 1e-5f);
        sSc[c] = sc; sSh[c] = bet[c] - m*sc;
    }
    __syncthreads();
    size_t u = (size_t)blockIdx.x * 256 + threadIdx.x;   // uint2 index
    uint2 H = ((const uint2*)g_Hrh)[u];
    uint2 L = ((const uint2*)g_Hrl)[u];
    int cb = (int)((u & 63) * 4);
    float e0, e1, e2, e3;
    unsplit2(H.x, L.x, e0, e1);
    unsplit2(H.y, L.y, e2, e3);
    e0 = fmaxf(fmaf(e0, sSc[cb],   sSh[cb]),   0.f);
    e1 = fmaxf(fmaf(e1, sSc[cb+1], sSh[cb+1]), 0.f);
    e2 = fmaxf(fmaf(e2, sSc[cb+2], sSh[cb+2]), 0.f);
    e3 = fmaxf(fmaf(e3, sSc[cb+3], sSh[cb+3]), 0.f);
    uint2 OH, OL;
    split2(e0, e1, OH.x, OL.x);
    split2(e2, e3, OH.y, OL.y);
    ((uint2*)g_Hbh)[u] = OH;
    ((uint2*)g_Hbl)[u] = OL;
}

// ---------------- split-K readout GEMM: [64,131072] @ [131072,128] ----------------
__global__ void __launch_bounds__(256) k_mlp1(const float* __restrict__ Wm1) {
    extern __shared__ uint32_t S[];   // 17920 words
    int kc0 = blockIdx.x;             // 0..255
    int kbase = kc0 * 512;
    int tid = threadIdx.x, w = tid >> 5, lane = tid & 31, g = lane >> 2, t = lane & 3;
    int wm = w & 3, wn = w >> 2;
    float acc[8][4];
#pragma unroll
    for (int ni=0;ni<8;ni++)
#pragma unroll
        for (int q=0;q<4;q++) acc[ni][q] = 0.f;

    {
        int kb0 = kbase;
        {
            int r = tid >> 2, q = (tid & 3) * 4;
            cpa(&S[r*STRA + q],        g_Hbh + (size_t)r*(FEAT/2) + (kb0>>1) + q);
            cpa(&S[1280 + r*STRA + q], g_Hbl + (size_t)r*(FEAT/2) + (kb0>>1) + q);
        }
#pragma unroll
        for (int i2 = 0; i2 < 4; i2++) {
            int idx = tid + i2*256;
            int rr = idx >> 5, c = (idx & 31) * 4;
            cpa(&S[5120 + rr*132 + c], Wm1 + (size_t)(kb0 + rr)*128 + c);
        }
        CP_COMMIT();
    }
    for (int it = 0; it < 16; it++) {
        CP_WAIT0();
        __syncthreads();
        if (it + 1 < 16) {
            int st = (it+1) & 1;
            int kb0 = kbase + (it+1)*32;
            {
                int r = tid >> 2, q = (tid & 3) * 4;
                cpa(&S[st*2560 + r*STRA + q],        g_Hbh + (size_t)r*(FEAT/2) + (kb0>>1) + q);
                cpa(&S[st*2560 + 1280 + r*STRA + q], g_Hbl + (size_t)r*(FEAT/2) + (kb0>>1) + q);
            }
#pragma unroll
            for (int i2 = 0; i2 < 4; i2++) {
                int idx = tid + i2*256;
                int rr = idx >> 5, c = (idx & 31) * 4;
                cpa(&S[5120 + st*4224 + rr*132 + c], Wm1 + (size_t)(kb0 + rr)*128 + c);
            }
            CP_COMMIT();
        }
        const float* braw = (const float*)(S + 5120 + (it&1)*4224);
#pragma unroll
        for (int i2 = 0; i2 < 2; i2++) {
            int idx = tid + i2*256;
            int kp = idx >> 5, c = (idx & 31) * 4;
            float4 u = *(const float4*)&braw[(2*kp  )*132 + c];
            float4 v = *(const float4*)&braw[(2*kp+1)*132 + c];
            uint4 H, L;
            split2(u.x, v.x, H.x, L.x);
            split2(u.y, v.y, H.y, L.y);
            split2(u.z, v.z, H.z, L.z);
            split2(u.w, v.w, H.w, L.w);
            *(uint4*)&S[13568 + kp*STRB + c] = H;
            *(uint4*)&S[15744 + kp*STRB + c] = L;
        }
        __syncthreads();
        const uint32_t* AH = S + (it&1)*2560;
        const uint32_t* AL = AH + 1280;
        const uint32_t* BH = S + 13568;
        const uint32_t* BL = S + 15744;
#pragma unroll
        for (int kb = 0; kb < 16; kb += 8) {
            uint32_t ah[4], al[4];
            int rb = wm*16;
            ah[0] = AH[(rb+g  )*STRA + kb+t  ]; al[0] = AL[(rb+g  )*STRA + kb+t  ];
            ah[1] = AH[(rb+g+8)*STRA + kb+t  ]; al[1] = AL[(rb+g+8)*STRA + kb+t  ];
            ah[2] = AH[(rb+g  )*STRA + kb+t+4]; al[2] = AL[(rb+g  )*STRA + kb+t+4];
            ah[3] = AH[(rb+g+8)*STRA + kb+t+4]; al[3] = AL[(rb+g+8)*STRA + kb+t+4];
#pragma unroll
            for (int ni=0;ni<8;ni++) {
                int cb = wn*64 + ni*8 + g;
                uint32_t bh[2], bl[2];
                bh[0] = BH[(kb+t  )*STRB + cb]; bl[0] = BL[(kb+t  )*STRB + cb];
                bh[1] = BH[(kb+t+4)*STRB + cb]; bl[1] = BL[(kb+t+4)*STRB + cb];
                mma16(acc[ni], ah, bh);
                mma16(acc[ni], ah, bl);
                mma16(acc[ni], al, bh);
            }
        }
    }
    float* out = g_Z1part + (size_t)kc0 * (B*M1);
    int r0 = wm*16 + g, r1 = r0 + 8;
#pragma unroll
    for (int ni=0;ni<8;ni++) {
        int c0 = wn*64 + ni*8 + 2*t;
        *(float2*)&out[r0*M1 + c0] = make_float2(acc[ni][0], acc[ni][1]);
        *(float2*)&out[r1*M1 + c0] = make_float2(acc[ni][2], acc[ni][3]);
    }
}

__global__ void k_red(const float* __restrict__ bm1) {
    int o = blockIdx.x*256 + threadIdx.x;   // 0..8191
    float s = bm1[o & 127];
    for (int kc = 0; kc < KCHUNKS; kc++) s += g_Z1part[(size_t)kc*(B*M1) + o];
    g_z1[o] = s;
}

// ---------------- head (exact fp32) ----------------
__global__ void __launch_bounds__(256) k_head(const float* __restrict__ gm1, const float* __restrict__ bem1,
                                              const float* __restrict__ Wm2, const float* __restrict__ bm2,
                                              const float* __restrict__ gm2, const float* __restrict__ bem2,
                                              const float* __restrict__ Wm3, const float* __restrict__ bm3,
                                              float* __restrict__ out) {
    __shared__ float sz1[64][128];
    __shared__ float sz2[64][64];
    int tid = threadIdx.x;

    if (tid < 128) {
        float s = 0.f, s2 = 0.f;
        for (int b = 0; b < 64; b++) { float v = g_z1[b*128 + tid]; s += v; s2 += v*v; }
        float m = s * (1.f/64.f), var = s2 * (1.f/64.f) - m*m;
        float sc = gm1[tid] * rsqrtf(var + 1e-5f);
        float sh = bem1[tid] - m*sc;
        for (int b = 0; b < 64; b++)
            sz1[b][tid] = fmaxf(fmaf(g_z1[b*128 + tid], sc, sh), 0.f);
    }
    __syncthreads();

    for (int o = tid; o < 4096; o += 256) {
        int b = o >> 6, j = o & 63;
        float s = bm2[j];
#pragma unroll 8
        for (int m = 0; m < 128; m++) s = fmaf(sz1[b][m], Wm2[m*64 + j], s);
        sz2[b][j] = s;
    }
    __syncthreads();

    if (tid < 64) {
        float s = 0.f, s2 = 0.f;
        for (int b = 0; b < 64; b++) { float v = sz2[b][tid]; s += v; s2 += v*v; }
        float m = s * (1.f/64.f), var = s2 * (1.f/64.f) - m*m;
        float sc = gm2[tid] * rsqrtf(var + 1e-5f);
        float sh = bem2[tid] - m*sc;
        for (int b = 0; b < 64; b++)
            sz2[b][tid] = fmaxf(fmaf(sz2[b][tid], sc, sh), 0.f);
    }
    __syncthreads();

    if (tid < 128) {
        int b = tid >> 1, c = tid & 1;
        float s = bm3[c];
#pragma unroll
        for (int j = 0; j < 64; j++) s = fmaf(sz2[b][j], Wm3[j*2 + c], s);
        out[b*2 + c] = s;
    }
}

// ---------------- launch ----------------
extern "C" void kernel_launch(void* const* d_in, const int* in_sizes, int n_in,
                              void* d_out, int out_size) {
    const float* x    = (const float*)d_in[0];
    const float* mask = (const float*)d_in[1];
    const float* W1   = (const float*)d_in[2];
    const float* b1   = (const float*)d_in[3];
    const float* g1   = (const float*)d_in[4];
    const float* be1  = (const float*)d_in[5];
    const float* W2   = (const float*)d_in[6];
    const float* b2   = (const float*)d_in[7];
    const float* g2   = (const float*)d_in[8];
    const float* be2  = (const float*)d_in[9];
    const float* Wm1  = (const float*)d_in[10];
    const float* bm1  = (const float*)d_in[11];
    const float* gm1  = (const float*)d_in[12];
    const float* bem1 = (const float*)d_in[13];
    const float* Wm2  = (const float*)d_in[14];
    const float* bm2  = (const float*)d_in[15];
    const float* gm2  = (const float*)d_in[16];
    const float* bem2 = (const float*)d_in[17];
    const float* Wm3  = (const float*)d_in[18];
    const float* bm3  = (const float*)d_in[19];
    float* out = (float*)d_out;

    static bool init = false;
    static uint32_t *pXch, *pXcl, *pHch, *pHcl, *pW1h, *pW1l, *pW2h, *pW2l;
    static float *pSum1, *pSq1, *pSum2, *pSq2;
    if (!init) {
        init = true;
        cudaFuncSetAttribute(k_layer, cudaFuncAttributeMaxDynamicSharedMemorySize, SMEM_LAYER_WORDS*4);
        cudaFuncSetAttribute(k_mlp1,  cudaFuncAttributeMaxDynamicSharedMemorySize, 17920*4);
        cudaGetSymbolAddress((void**)&pXch, g_Xch);
        cudaGetSymbolAddress((void**)&pXcl, g_Xcl);
        cudaGetSymbolAddress((void**)&pHch, g_Hch);
        cudaGetSymbolAddress((void**)&pHcl, g_Hcl);
        cudaGetSymbolAddress((void**)&pW1h, g_W1h);
        cudaGetSymbolAddress((void**)&pW1l, g_W1l);
        cudaGetSymbolAddress((void**)&pW2h, g_W2h);
        cudaGetSymbolAddress((void**)&pW2l, g_W2l);
        cudaGetSymbolAddress((void**)&pSum1, g_sum1);
        cudaGetSymbolAddress((void**)&pSq1,  g_sumsq1);
        cudaGetSymbolAddress((void**)&pSum2, g_sum2);
        cudaGetSymbolAddress((void**)&pSq2,  g_sumsq2);
    }

    // prep
    k_invn<<<NROWS/8, 256>>>(x);
    k_splitX<<<(NROWS/2)*(DD/4)/256, 256>>>(x);
    k_splitW<<<64, 256>>>(W1, W2);
    k_simA<<<B*NSUB, 256>>>(mask);

    // GCN layer 1 (fully fused)
    k_layer<<<256, 512, SMEM_LAYER_WORDS*4>>>(pXch, pXcl, pW1h, pW1l, b1, pSum1, pSq1);
    k_bnpass1<<<256, 256>>>(g1, be1);

    // GCN layer 2 (fully fused)
    k_layer<<<256, 512, SMEM_LAYER_WORDS*4>>>(pHch, pHcl, pW2h, pW2l, b2, pSum2, pSq2);
    k_bnpass2<<<(int)((size_t)NROWS*128/2/256), 256>>>(g2, be2);

    // readout + head
    k_mlp1<<<KCHUNKS, 256, 17920*4>>>(Wm1);
    k_red<<<32, 256>>>(bm1);
    k_head<<<1, 256>>>(gm1, bem1, Wm2, bm2, gm2, bem2, Wm3, bm3, out);
}

// round 8
// speedup vs baseline: 1.0799x; 1.0799x over previous
#include <cuda_runtime.h>
#include <cuda_bf16.h>
#include <math.h>
#include <stdint.h>

#define B     64
#define NSUB  4
#define PP    128
#define TP    512
#define DD    256
#define HH    256
#define FEAT  131072
#define M1    128
#define NROWS (B*TP)            // 32768
#define KCHUNKS 256             // split-K chunks for mlp1 (512 K each)

#define STRA  20                // A-tile row stride (16 kpair words + 4 pad)
#define STRB  136               // B-tile row stride (128 cols + 8 pad)

#define SIMA_STG   5120         // per-stage words in k_simA (A hi 2560 + A lo 2560)
#define GEMM_STG   9472         // per-stage words in k_xw/k_bmm (A 5120 + B 4352)
#define MLP_STG    6912         // per-stage words in k_mlp1 (A 2560 + B 4352)

// ---------------- scratch (device globals; no allocation) ----------------
__device__ float    g_invn[B*TP];
__device__ float    g_dinv[B*TP];
__device__ uint32_t g_Xh[(size_t)NROWS*128];       // x rowK split
__device__ uint32_t g_Xl[(size_t)NROWS*128];
__device__ uint32_t g_Ah[(size_t)256*PP*64];       // adjacency (raw, diag=1) kpair packed
__device__ uint32_t g_Al[(size_t)256*PP*64];
__device__ uint32_t g_W1h[128*256], g_W1l[128*256];
__device__ uint32_t g_W2h[128*256], g_W2l[128*256];
__device__ uint32_t g_Wm1h[(size_t)(FEAT/2)*128];  // Wm1 kpairN split (33.5 MB each)
__device__ uint32_t g_Wm1l[(size_t)(FEAT/2)*128];
__device__ uint32_t g_XWh[(size_t)(NROWS/2)*256];  // XW*dinv+bias, kpairN packed
__device__ uint32_t g_XWl[(size_t)(NROWS/2)*256];
__device__ float    g_Hb[(size_t)NROWS*HH];        // pre-BN h (fp32)
__device__ uint32_t g_Hbh[(size_t)NROWS*128];      // post-BN h split (rowK packed)
__device__ uint32_t g_Hbl[(size_t)NROWS*128];
__device__ float    g_sum1[HH], g_sumsq1[HH], g_sum2[HH], g_sumsq2[HH];
__device__ float    g_Z1part[(size_t)KCHUNKS*B*M1];
__device__ float    g_z1[B*M1];

// ---------------- helpers ----------------
__device__ __forceinline__ void split2(float a, float b, uint32_t& h, uint32_t& l) {
    __nv_bfloat162 hb = __floats2bfloat162_rn(a, b);
    float2 hf = __bfloat1622float2(hb);
    __nv_bfloat162 lb = __floats2bfloat162_rn(a - hf.x, b - hf.y);
    h = *(uint32_t*)&hb;
    l = *(uint32_t*)&lb;
}
__device__ __forceinline__ void mma16(float* c, const uint32_t* a, const uint32_t* b) {
    asm volatile("mma.sync.aligned.m16n8k16.row.col.f32.bf16.bf16.f32 "
                 "{%0,%1,%2,%3}, {%4,%5,%6,%7}, {%8,%9}, {%0,%1,%2,%3};\n"
                 : "+f"(c[0]), "+f"(c[1]), "+f"(c[2]), "+f"(c[3])
                 : "r"(a[0]), "r"(a[1]), "r"(a[2]), "r"(a[3]),
                   "r"(b[0]), "r"(b[1]));
}
__device__ __forceinline__ void cpa(uint32_t* dst, const void* src) {
    uint32_t d = (uint32_t)__cvta_generic_to_shared(dst);
    asm volatile("cp.async.cg.shared.global [%0], [%1], 16;" :: "r"(d), "l"(src));
}
#define CP_COMMIT() asm volatile("cp.async.commit_group;")
#define CP_WAIT0()  asm volatile("cp.async.wait_group 0;")
#define CP_WAIT1()  asm volatile("cp.async.wait_group 1;")

// ---------------- prep: 1/||x_row||, rowK split of x, zero BN accumulators ----------------
__global__ void __launch_bounds__(256) k_prep(const float* __restrict__ x) {
    __shared__ float sX[8][260];
    int tid = threadIdx.x, w = tid >> 5, lane = tid & 31;
    if (blockIdx.x == 0) {
        g_sum1[tid] = 0.f; g_sumsq1[tid] = 0.f;
        g_sum2[tid] = 0.f; g_sumsq2[tid] = 0.f;
    }
    int row = blockIdx.x * 8 + w;
    const float* xr = x + (size_t)row * DD;
    float s = 0.f;
#pragma unroll
    for (int i = 0; i < 8; i++) {
        float v = xr[lane + 32*i];
        sX[w][lane + 32*i] = v;
        s += v*v;
    }
#pragma unroll
    for (int o = 16; o; o >>= 1) s += __shfl_xor_sync(0xffffffffu, s, o);
    if (lane == 0) g_invn[row] = 1.0f / fmaxf(sqrtf(s), 1e-12f);
    __syncthreads();
    {
        int tr = tid >> 5;
        int c0 = (tid & 31) * 8;
        uint4 H, L;
        split2(sX[tr][c0+0], sX[tr][c0+1], H.x, L.x);
        split2(sX[tr][c0+2], sX[tr][c0+3], H.y, L.y);
        split2(sX[tr][c0+4], sX[tr][c0+5], H.z, L.z);
        split2(sX[tr][c0+6], sX[tr][c0+7], H.w, L.w);
        size_t o = (size_t)(blockIdx.x*8 + tr)*128 + (c0 >> 1);
        *(uint4*)&g_Xh[o] = H;
        *(uint4*)&g_Xl[o] = L;
    }
}

// ---------------- split W1/W2 -> kpairN packed ----------------
__global__ void k_splitW(const float* __restrict__ W1, const float* __restrict__ W2) {
    int blk = blockIdx.x;
    const float* W = (blk < 32) ? W1 : W2;
    uint32_t* Wh = (blk < 32) ? g_W1h : g_W2h;
    uint32_t* Wl = (blk < 32) ? g_W1l : g_W2l;
    int idx = (blk & 31) * 256 + threadIdx.x;
    int kp = idx >> 6, c = (idx & 63) * 4;
    float4 a = *(const float4*)&W[(2*kp)*256 + c];
    float4 b = *(const float4*)&W[(2*kp+1)*256 + c];
    uint4 H, L;
    split2(a.x, b.x, H.x, L.x);
    split2(a.y, b.y, H.y, L.y);
    split2(a.z, b.z, H.z, L.z);
    split2(a.w, b.w, H.w, L.w);
    *(uint4*)&Wh[kp*256 + c] = H;
    *(uint4*)&Wl[kp*256 + c] = L;
}

// ---------------- split Wm1 [131072,128] -> kpairN packed ----------------
__global__ void k_splitWm1(const float* __restrict__ Wm1) {
    size_t idx = (size_t)blockIdx.x * 256 + threadIdx.x;   // 2M tasks
    size_t kp = idx >> 5;
    int c = (int)(idx & 31) * 4;
    float4 a = *(const float4*)(Wm1 + (2*kp)*128 + c);
    float4 b = *(const float4*)(Wm1 + (2*kp+1)*128 + c);
    uint4 H, L;
    split2(a.x, b.x, H.x, L.x);
    split2(a.y, b.y, H.y, L.y);
    split2(a.z, b.z, H.z, L.z);
    split2(a.w, b.w, H.w, L.w);
    *(uint4*)&g_Wm1h[kp*128 + c] = H;
    *(uint4*)&g_Wm1l[kp*128 + c] = L;
}

// ---------------- per-(b,n): A = (cos+1)/2*mask, diag=1 -> g_Ah/l; dinv ----------------
__global__ void __launch_bounds__(256) k_simA(const float* __restrict__ mask) {
    extern __shared__ uint32_t S[];   // 3 * SIMA_STG
    __shared__ float sInv[128];
    __shared__ float sdeg[128];
    int bn = blockIdx.x;
    int rowbase = bn * 128;
    int tid = threadIdx.x, w = tid >> 5, lane = tid & 31, g = lane >> 2, t = lane & 3;
    int wm = w & 3, wn = w >> 2;
    if (tid < 128) { sInv[tid] = g_invn[rowbase + tid]; sdeg[tid] = 0.f; }

    float acc[2][8][4];
#pragma unroll
    for (int mi=0;mi<2;mi++)
#pragma unroll
        for (int ni=0;ni<8;ni++)
#pragma unroll
            for (int q=0;q<4;q++) acc[mi][ni][q] = 0.f;

#pragma unroll 1
    for (int pc = 0; pc < 2; pc++) {
        int st = (pc % 3) * SIMA_STG;
#pragma unroll
        for (int i2 = 0; i2 < 2; i2++) {
            int idx = tid + i2*256;
            int r = idx >> 2, q = (idx & 3) * 4;
            cpa(&S[st + r*STRA + q],        g_Xh + (size_t)(rowbase + r)*128 + pc*16 + q);
            cpa(&S[st + 2560 + r*STRA + q], g_Xl + (size_t)(rowbase + r)*128 + pc*16 + q);
        }
        CP_COMMIT();
    }
#pragma unroll 1
    for (int it = 0; it < 8; it++) {
        if (it < 7) { CP_WAIT1(); } else { CP_WAIT0(); }
        __syncthreads();
        if (it + 2 < 8) {
            int c = it + 2, st = (c % 3) * SIMA_STG;
#pragma unroll
            for (int i2 = 0; i2 < 2; i2++) {
                int idx = tid + i2*256;
                int r = idx >> 2, q = (idx & 3) * 4;
                cpa(&S[st + r*STRA + q],        g_Xh + (size_t)(rowbase + r)*128 + c*16 + q);
                cpa(&S[st + 2560 + r*STRA + q], g_Xl + (size_t)(rowbase + r)*128 + c*16 + q);
            }
            CP_COMMIT();
        }
        const uint32_t* H = S + (it % 3) * SIMA_STG;
        const uint32_t* L = H + 2560;
#pragma unroll
        for (int kb = 0; kb < 16; kb += 8) {
            uint32_t ah[2][4], al[2][4];
#pragma unroll
            for (int mi=0;mi<2;mi++) {
                int rb = wm*32 + mi*16;
                ah[mi][0] = H[(rb+g  )*STRA + kb+t  ]; al[mi][0] = L[(rb+g  )*STRA + kb+t  ];
                ah[mi][1] = H[(rb+g+8)*STRA + kb+t  ]; al[mi][1] = L[(rb+g+8)*STRA + kb+t  ];
                ah[mi][2] = H[(rb+g  )*STRA + kb+t+4]; al[mi][2] = L[(rb+g  )*STRA + kb+t+4];
                ah[mi][3] = H[(rb+g+8)*STRA + kb+t+4]; al[mi][3] = L[(rb+g+8)*STRA + kb+t+4];
            }
#pragma unroll
            for (int ni=0;ni<8;ni++) {
                int cb = wn*64 + ni*8 + g;
                uint32_t bh[2], bl[2];
                bh[0] = H[cb*STRA + kb+t];   bl[0] = L[cb*STRA + kb+t];
                bh[1] = H[cb*STRA + kb+t+4]; bl[1] = L[cb*STRA + kb+t+4];
#pragma unroll
                for (int mi=0;mi<2;mi++) {
                    mma16(acc[mi][ni], ah[mi], bh);
                    mma16(acc[mi][ni], ah[mi], bl);
                    mma16(acc[mi][ni], al[mi], bh);
                }
            }
        }
    }
    __syncthreads();

#pragma unroll
    for (int ni=0;ni<8;ni++) {
        int c0 = wn*64 + ni*8 + 2*t, c1 = c0 + 1;
        int cp = c0 >> 1;
        float ic0 = sInv[c0], ic1 = sInv[c1];
#pragma unroll
        for (int mi=0;mi<2;mi++) {
            int r0 = wm*32 + mi*16 + g, r1 = r0 + 8;
            float i0 = sInv[r0], i1 = sInv[r1];
            float v00 = (r0==c0) ? 1.f : (acc[mi][ni][0]*i0*ic0 + 1.f)*0.5f*mask[r0*PP+c0];
            float v01 = (r0==c1) ? 1.f : (acc[mi][ni][1]*i0*ic1 + 1.f)*0.5f*mask[r0*PP+c1];
            float v10 = (r1==c0) ? 1.f : (acc[mi][ni][2]*i1*ic0 + 1.f)*0.5f*mask[r1*PP+c0];
            float v11 = (r1==c1) ? 1.f : (acc[mi][ni][3]*i1*ic1 + 1.f)*0.5f*mask[r1*PP+c1];
            uint32_t h, l;
            split2(v00, v01, h, l);
            g_Ah[((size_t)bn*128 + r0)*64 + cp] = h;
            g_Al[((size_t)bn*128 + r0)*64 + cp] = l;
            split2(v10, v11, h, l);
            g_Ah[((size_t)bn*128 + r1)*64 + cp] = h;
            g_Al[((size_t)bn*128 + r1)*64 + cp] = l;
            atomicAdd(&sdeg[r0], v00 + v01);
            atomicAdd(&sdeg[r1], v10 + v11);
        }
    }
    __syncthreads();
    if (tid < 128) {
        float deg = sdeg[tid];
        g_dinv[rowbase + tid] = (deg > 0.f) ? rsqrtf(fmaxf(deg, 1e-12f)) : 0.f;
    }
}

// ---------------- XW = A @ W, epilogue (acc+bias)*dinv -> g_XWh/l kpairN ----------------
__global__ void __launch_bounds__(256) k_xw(const uint32_t* __restrict__ Ah,
                                            const uint32_t* __restrict__ Al,
                                            const uint32_t* __restrict__ Wh,
                                            const uint32_t* __restrict__ Wl,
                                            const float* __restrict__ bias) {
    extern __shared__ uint32_t S[];   // 3 * GEMM_STG
    __shared__ float sDv[128];
    int tid = threadIdx.x, w = tid >> 5, lane = tid & 31, g = lane >> 2, t = lane & 3;
    int wm = w & 3, wn = w >> 2;
    int m0 = blockIdx.y * 128, n0 = blockIdx.x * 128;
    if (tid < 128) sDv[tid] = g_dinv[m0 + tid];

    float acc[2][8][4];
#pragma unroll
    for (int mi=0;mi<2;mi++)
#pragma unroll
        for (int ni=0;ni<8;ni++)
#pragma unroll
            for (int q=0;q<4;q++) acc[mi][ni][q] = 0.f;

#pragma unroll 1
    for (int pc = 0; pc < 2; pc++) {
        int st = (pc % 3) * GEMM_STG;
#pragma unroll
        for (int i2 = 0; i2 < 2; i2++) {
            int idx = tid + i2*256;
            int r = idx >> 2, q = (idx & 3) * 4;
            cpa(&S[st + r*STRA + q],        Ah + (size_t)(m0 + r)*128 + pc*16 + q);
            cpa(&S[st + 2560 + r*STRA + q], Al + (size_t)(m0 + r)*128 + pc*16 + q);
        }
#pragma unroll
        for (int i2 = 0; i2 < 2; i2++) {
            int idx = tid + i2*256;
            int kp = idx >> 5, cc = (idx & 31) * 4;
            cpa(&S[st + 5120 + kp*STRB + cc],        Wh + (size_t)(pc*16 + kp)*256 + n0 + cc);
            cpa(&S[st + 5120 + 2176 + kp*STRB + cc], Wl + (size_t)(pc*16 + kp)*256 + n0 + cc);
        }
        CP_COMMIT();
    }
#pragma unroll 1
    for (int it = 0; it < 8; it++) {
        if (it < 7) { CP_WAIT1(); } else { CP_WAIT0(); }
        __syncthreads();
        if (it + 2 < 8) {
            int c = it + 2, st = (c % 3) * GEMM_STG;
#pragma unroll
            for (int i2 = 0; i2 < 2; i2++) {
                int idx = tid + i2*256;
                int r = idx >> 2, q = (idx & 3) * 4;
                cpa(&S[st + r*STRA + q],        Ah + (size_t)(m0 + r)*128 + c*16 + q);
                cpa(&S[st + 2560 + r*STRA + q], Al + (size_t)(m0 + r)*128 + c*16 + q);
            }
#pragma unroll
            for (int i2 = 0; i2 < 2; i2++) {
                int idx = tid + i2*256;
                int kp = idx >> 5, cc = (idx & 31) * 4;
                cpa(&S[st + 5120 + kp*STRB + cc],        Wh + (size_t)(c*16 + kp)*256 + n0 + cc);
                cpa(&S[st + 5120 + 2176 + kp*STRB + cc], Wl + (size_t)(c*16 + kp)*256 + n0 + cc);
            }
            CP_COMMIT();
        }
        const uint32_t* AH = S + (it % 3) * GEMM_STG;
        const uint32_t* AL = AH + 2560;
        const uint32_t* BH = AH + 5120;
        const uint32_t* BL = BH + 2176;
#pragma unroll
        for (int kb = 0; kb < 16; kb += 8) {
            uint32_t ah[2][4], al[2][4];
#pragma unroll
            for (int mi=0;mi<2;mi++) {
                int rb = wm*32 + mi*16;
                ah[mi][0] = AH[(rb+g  )*STRA + kb+t  ]; al[mi][0] = AL[(rb+g  )*STRA + kb+t  ];
                ah[mi][1] = AH[(rb+g+8)*STRA + kb+t  ]; al[mi][1] = AL[(rb+g+8)*STRA + kb+t  ];
                ah[mi][2] = AH[(rb+g  )*STRA + kb+t+4]; al[mi][2] = AL[(rb+g  )*STRA + kb+t+4];
                ah[mi][3] = AH[(rb+g+8)*STRA + kb+t+4]; al[mi][3] = AL[(rb+g+8)*STRA + kb+t+4];
            }
#pragma unroll
            for (int ni=0;ni<8;ni++) {
                int cb = wn*64 + ni*8 + g;
                uint32_t bh[2], bl[2];
                bh[0] = BH[(kb+t  )*STRB + cb]; bl[0] = BL[(kb+t  )*STRB + cb];
                bh[1] = BH[(kb+t+4)*STRB + cb]; bl[1] = BL[(kb+t+4)*STRB + cb];
#pragma unroll
                for (int mi=0;mi<2;mi++) {
                    mma16(acc[mi][ni], ah[mi], bh);
                    mma16(acc[mi][ni], ah[mi], bl);
                    mma16(acc[mi][ni], al[mi], bh);
                }
            }
        }
    }
    // epilogue: (acc + bias) * dinv -> smem staging -> packed kpairN global
    __syncthreads();
    float* stg = (float*)S;   // 128 x 132 floats = 16896 words
#pragma unroll
    for (int mi=0;mi<2;mi++) {
        int r0 = wm*32 + mi*16 + g, r1 = r0 + 8;
        float d0 = sDv[r0], d1 = sDv[r1];
#pragma unroll
        for (int ni=0;ni<8;ni++) {
            int c0 = wn*64 + ni*8 + 2*t;
            float b0 = bias[n0 + c0], b1 = bias[n0 + c0 + 1];
            *(float2*)&stg[r0*132 + c0] = make_float2((acc[mi][ni][0]+b0)*d0, (acc[mi][ni][1]+b1)*d0);
            *(float2*)&stg[r1*132 + c0] = make_float2((acc[mi][ni][2]+b0)*d1, (acc[mi][ni][3]+b1)*d1);
        }
    }
    __syncthreads();
#pragma unroll
    for (int i2 = 0; i2 < 8; i2++) {
        int idx = tid + i2*256;
        int kp = idx >> 5, c = (idx & 31) * 4;
        float4 u = *(float4*)&stg[(2*kp  )*132 + c];
        float4 v = *(float4*)&stg[(2*kp+1)*132 + c];
        uint4 H, L;
        split2(u.x, v.x, H.x, L.x);
        split2(u.y, v.y, H.y, L.y);
        split2(u.z, v.z, H.z, L.z);
        split2(u.w, v.w, H.w, L.w);
        *(uint4*)&g_XWh[((size_t)(m0>>1) + kp)*256 + n0 + c] = H;
        *(uint4*)&g_XWl[((size_t)(m0>>1) + kp)*256 + n0 + c] = L;
    }
}

// ---------------- H = dinv_i * A(bn) @ XWs + fused BN stats -> g_Hb ----------------
__global__ void __launch_bounds__(256) k_bmm(float* __restrict__ sumArr,
                                             float* __restrict__ sqArr) {
    extern __shared__ uint32_t S[];   // 3 * GEMM_STG
    __shared__ float sDv[128];
    __shared__ float sSum[128], sSq[128];
    int bn = blockIdx.y;
    int h0 = blockIdx.x * 128;
    int rowbase = bn * 128;
    int tid = threadIdx.x, w = tid >> 5, lane = tid & 31, g = lane >> 2, t = lane & 3;
    int wm = w & 3, wn = w >> 2;
    if (tid < 128) { sDv[tid] = g_dinv[rowbase + tid]; sSum[tid] = 0.f; sSq[tid] = 0.f; }

    float acc[2][8][4];
#pragma unroll
    for (int mi=0;mi<2;mi++)
#pragma unroll
        for (int ni=0;ni<8;ni++)
#pragma unroll
            for (int q=0;q<4;q++) acc[mi][ni][q] = 0.f;

#pragma unroll 1
    for (int pc = 0; pc < 2; pc++) {
        int st = (pc % 3) * GEMM_STG;
#pragma unroll
        for (int i2 = 0; i2 < 2; i2++) {
            int idx = tid + i2*256;
            int r = idx >> 2, q = (idx & 3) * 4;
            cpa(&S[st + r*STRA + q],        g_Ah + ((size_t)bn*128 + r)*64 + pc*16 + q);
            cpa(&S[st + 2560 + r*STRA + q], g_Al + ((size_t)bn*128 + r)*64 + pc*16 + q);
        }
#pragma unroll
        for (int i2 = 0; i2 < 2; i2++) {
            int idx = tid + i2*256;
            int kp = idx >> 5, cc = (idx & 31) * 4;
            cpa(&S[st + 5120 + kp*STRB + cc],        g_XWh + ((size_t)(bn*64) + pc*16 + kp)*256 + h0 + cc);
            cpa(&S[st + 5120 + 2176 + kp*STRB + cc], g_XWl + ((size_t)(bn*64) + pc*16 + kp)*256 + h0 + cc);
        }
        CP_COMMIT();
    }
#pragma unroll 1
    for (int it = 0; it < 4; it++) {
        if (it < 3) { CP_WAIT1(); } else { CP_WAIT0(); }
        __syncthreads();
        if (it + 2 < 4) {
            int c = it + 2, st = (c % 3) * GEMM_STG;
#pragma unroll
            for (int i2 = 0; i2 < 2; i2++) {
                int idx = tid + i2*256;
                int r = idx >> 2, q = (idx & 3) * 4;
                cpa(&S[st + r*STRA + q],        g_Ah + ((size_t)bn*128 + r)*64 + c*16 + q);
                cpa(&S[st + 2560 + r*STRA + q], g_Al + ((size_t)bn*128 + r)*64 + c*16 + q);
            }
#pragma unroll
            for (int i2 = 0; i2 < 2; i2++) {
                int idx = tid + i2*256;
                int kp = idx >> 5, cc = (idx & 31) * 4;
                cpa(&S[st + 5120 + kp*STRB + cc],        g_XWh + ((size_t)(bn*64) + c*16 + kp)*256 + h0 + cc);
                cpa(&S[st + 5120 + 2176 + kp*STRB + cc], g_XWl + ((size_t)(bn*64) + c*16 + kp)*256 + h0 + cc);
            }
            CP_COMMIT();
        }
        const uint32_t* AH = S + (it % 3) * GEMM_STG;
        const uint32_t* AL = AH + 2560;
        const uint32_t* BH = AH + 5120;
        const uint32_t* BL = BH + 2176;
#pragma unroll
        for (int kb = 0; kb < 16; kb += 8) {
            uint32_t ah[2][4], al[2][4];
#pragma unroll
            for (int mi=0;mi<2;mi++) {
                int rb = wm*32 + mi*16;
                ah[mi][0] = AH[(rb+g  )*STRA + kb+t  ]; al[mi][0] = AL[(rb+g  )*STRA + kb+t  ];
                ah[mi][1] = AH[(rb+g+8)*STRA + kb+t  ]; al[mi][1] = AL[(rb+g+8)*STRA + kb+t  ];
                ah[mi][2] = AH[(rb+g  )*STRA + kb+t+4]; al[mi][2] = AL[(rb+g  )*STRA + kb+t+4];
                ah[mi][3] = AH[(rb+g+8)*STRA + kb+t+4]; al[mi][3] = AL[(rb+g+8)*STRA + kb+t+4];
            }
#pragma unroll
            for (int ni=0;ni<8;ni++) {
                int cb = wn*64 + ni*8 + g;
                uint32_t bh[2], bl[2];
                bh[0] = BH[(kb+t  )*STRB + cb]; bl[0] = BL[(kb+t  )*STRB + cb];
                bh[1] = BH[(kb+t+4)*STRB + cb]; bl[1] = BL[(kb+t+4)*STRB + cb];
#pragma unroll
                for (int mi=0;mi<2;mi++) {
                    mma16(acc[mi][ni], ah[mi], bh);
                    mma16(acc[mi][ni], ah[mi], bl);
                    mma16(acc[mi][ni], al[mi], bh);
                }
            }
        }
    }
    float* base = g_Hb + (size_t)rowbase * HH;
#pragma unroll
    for (int ni=0;ni<8;ni++) {
        int cl = wn*64 + ni*8 + 2*t;
        float cs0 = 0.f, cs1 = 0.f, cq0 = 0.f, cq1 = 0.f;
#pragma unroll
        for (int mi=0;mi<2;mi++) {
            int r0 = wm*32 + mi*16 + g, r1 = r0 + 8;
            float d0 = sDv[r0], d1 = sDv[r1];
            float v00 = acc[mi][ni][0]*d0, v01 = acc[mi][ni][1]*d0;
            float v10 = acc[mi][ni][2]*d1, v11 = acc[mi][ni][3]*d1;
            *(float2*)&base[(size_t)r0*HH + h0 + cl] = make_float2(v00, v01);
            *(float2*)&base[(size_t)r1*HH + h0 + cl] = make_float2(v10, v11);
            cs0 += v00 + v10; cs1 += v01 + v11;
            cq0 += v00*v00 + v10*v10; cq1 += v01*v01 + v11*v11;
        }
        atomicAdd(&sSum[cl],   cs0);
        atomicAdd(&sSum[cl+1], cs1);
        atomicAdd(&sSq[cl],    cq0);
        atomicAdd(&sSq[cl+1],  cq1);
    }
    __syncthreads();
    if (tid < 128) {
        atomicAdd(&sumArr[h0 + tid], sSum[tid]);
        atomicAdd(&sqArr[h0 + tid],  sSq[tid]);
    }
}

// ---------------- bnsplit (finalize folded): g_Hb -> g_Hbh/l (rowK) ----------------
__global__ void __launch_bounds__(256) k_bnsplit(const float* __restrict__ sumArr,
                                                 const float* __restrict__ sqArr,
                                                 const float* __restrict__ gam,
                                                 const float* __restrict__ bet) {
    __shared__ float sSc[256], sSh[256];
    {
        int c = threadIdx.x;
        const float invn = 1.0f / (float)NROWS;
        float m = sumArr[c] * invn;
        float v = sqArr[c] * invn - m*m;
        float sc = gam[c] * rsqrtf(v + 1e-5f);
        sSc[c] = sc; sSh[c] = bet[c] - m*sc;
    }
    __syncthreads();
    size_t i4 = (size_t)blockIdx.x * 256 + threadIdx.x;
    float4 v = ((const float4*)g_Hb)[i4];
    int c = (int)((i4 * 4) & 255);
    v.x = fmaxf(fmaf(v.x, sSc[c],   sSh[c]),   0.f);
    v.y = fmaxf(fmaf(v.y, sSc[c+1], sSh[c+1]), 0.f);
    v.z = fmaxf(fmaf(v.z, sSc[c+2], sSh[c+2]), 0.f);
    v.w = fmaxf(fmaf(v.w, sSc[c+3], sSh[c+3]), 0.f);
    uint32_t h0, l0, h1, l1;
    split2(v.x, v.y, h0, l0);
    split2(v.z, v.w, h1, l1);
    ((uint2*)g_Hbh)[i4] = make_uint2(h0, h1);
    ((uint2*)g_Hbl)[i4] = make_uint2(l0, l1);
}

// ---------------- split-K readout GEMM (pure-copy fills, 3-stage) ----------------
__global__ void __launch_bounds__(256) k_mlp1() {
    extern __shared__ uint32_t S[];   // 3 * MLP_STG
    int kc0 = blockIdx.x;             // 0..255
    size_t kwb = (size_t)kc0 * 256;   // word base into FEAT/2
    int tid = threadIdx.x, w = tid >> 5, lane = tid & 31, g = lane >> 2, t = lane & 3;
    int wm = w & 3, wn = w >> 2;
    float acc[8][4];
#pragma unroll
    for (int ni=0;ni<8;ni++)
#pragma unroll
        for (int q=0;q<4;q++) acc[ni][q] = 0.f;

#pragma unroll 1
    for (int pc = 0; pc < 2; pc++) {
        int st = (pc % 3) * MLP_STG;
        {
            int r = tid >> 2, q = (tid & 3) * 4;
            cpa(&S[st + r*STRA + q],        g_Hbh + (size_t)r*(FEAT/2) + kwb + pc*16 + q);
            cpa(&S[st + 1280 + r*STRA + q], g_Hbl + (size_t)r*(FEAT/2) + kwb + pc*16 + q);
        }
#pragma unroll
        for (int i2 = 0; i2 < 2; i2++) {
            int idx = tid + i2*256;
            int kp = idx >> 5, cc = (idx & 31) * 4;
            cpa(&S[st + 2560 + kp*STRB + cc],        g_Wm1h + (kwb + pc*16 + kp)*128 + cc);
            cpa(&S[st + 2560 + 2176 + kp*STRB + cc], g_Wm1l + (kwb + pc*16 + kp)*128 + cc);
        }
        CP_COMMIT();
    }
#pragma unroll 1
    for (int it = 0; it < 16; it++) {
        if (it < 15) { CP_WAIT1(); } else { CP_WAIT0(); }
        __syncthreads();
        if (it + 2 < 16) {
            int c = it + 2, st = (c % 3) * MLP_STG;
            {
                int r = tid >> 2, q = (tid & 3) * 4;
                cpa(&S[st + r*STRA + q],        g_Hbh + (size_t)r*(FEAT/2) + kwb + c*16 + q);
                cpa(&S[st + 1280 + r*STRA + q], g_Hbl + (size_t)r*(FEAT/2) + kwb + c*16 + q);
            }
#pragma unroll
            for (int i2 = 0; i2 < 2; i2++) {
                int idx = tid + i2*256;
                int kp = idx >> 5, cc = (idx & 31) * 4;
                cpa(&S[st + 2560 + kp*STRB + cc],        g_Wm1h + (kwb + c*16 + kp)*128 + cc);
                cpa(&S[st + 2560 + 2176 + kp*STRB + cc], g_Wm1l + (kwb + c*16 + kp)*128 + cc);
            }
            CP_COMMIT();
        }
        const uint32_t* AH = S + (it % 3) * MLP_STG;
        const uint32_t* AL = AH + 1280;
        const uint32_t* BH = AH + 2560;
        const uint32_t* BL = BH + 2176;
#pragma unroll
        for (int kb = 0; kb < 16; kb += 8) {
            uint32_t ah[4], al[4];
            int rb = wm*16;
            ah[0] = AH[(rb+g  )*STRA + kb+t  ]; al[0] = AL[(rb+g  )*STRA + kb+t  ];
            ah[1] = AH[(rb+g+8)*STRA + kb+t  ]; al[1] = AL[(rb+g+8)*STRA + kb+t  ];
            ah[2] = AH[(rb+g  )*STRA + kb+t+4]; al[2] = AL[(rb+g  )*STRA + kb+t+4];
            ah[3] = AH[(rb+g+8)*STRA + kb+t+4]; al[3] = AL[(rb+g+8)*STRA + kb+t+4];
#pragma unroll
            for (int ni=0;ni<8;ni++) {
                int cb = wn*64 + ni*8 + g;
                uint32_t bh[2], bl[2];
                bh[0] = BH[(kb+t  )*STRB + cb]; bl[0] = BL[(kb+t  )*STRB + cb];
                bh[1] = BH[(kb+t+4)*STRB + cb]; bl[1] = BL[(kb+t+4)*STRB + cb];
                mma16(acc[ni], ah, bh);
                mma16(acc[ni], ah, bl);
                mma16(acc[ni], al, bh);
            }
        }
    }
    float* out = g_Z1part + (size_t)kc0 * (B*M1);
    int r0 = wm*16 + g, r1 = r0 + 8;
#pragma unroll
    for (int ni=0;ni<8;ni++) {
        int c0 = wn*64 + ni*8 + 2*t;
        *(float2*)&out[r0*M1 + c0] = make_float2(acc[ni][0], acc[ni][1]);
        *(float2*)&out[r1*M1 + c0] = make_float2(acc[ni][2], acc[ni][3]);
    }
}

__global__ void k_red(const float* __restrict__ bm1) {
    int o = blockIdx.x*256 + threadIdx.x;   // 0..8191
    float s = bm1[o & 127];
    for (int kc = 0; kc < KCHUNKS; kc++) s += g_Z1part[(size_t)kc*(B*M1) + o];
    g_z1[o] = s;
}

// ---------------- head (exact fp32) ----------------
__global__ void __launch_bounds__(256) k_head(const float* __restrict__ gm1, const float* __restrict__ bem1,
                                              const float* __restrict__ Wm2, const float* __restrict__ bm2,
                                              const float* __restrict__ gm2, const float* __restrict__ bem2,
                                              const float* __restrict__ Wm3, const float* __restrict__ bm3,
                                              float* __restrict__ out) {
    __shared__ float sz1[64][128];
    __shared__ float sz2[64][64];
    int tid = threadIdx.x;

    if (tid < 128) {
        float s = 0.f, s2 = 0.f;
        for (int b = 0; b < 64; b++) { float v = g_z1[b*128 + tid]; s += v; s2 += v*v; }
        float m = s * (1.f/64.f), var = s2 * (1.f/64.f) - m*m;
        float sc = gm1[tid] * rsqrtf(var + 1e-5f);
        float sh = bem1[tid] - m*sc;
        for (int b = 0; b < 64; b++)
            sz1[b][tid] = fmaxf(fmaf(g_z1[b*128 + tid], sc, sh), 0.f);
    }
    __syncthreads();

    for (int o = tid; o < 4096; o += 256) {
        int b = o >> 6, j = o & 63;
        float s = bm2[j];
#pragma unroll 8
        for (int m = 0; m < 128; m++) s = fmaf(sz1[b][m], Wm2[m*64 + j], s);
        sz2[b][j] = s;
    }
    __syncthreads();

    if (tid < 64) {
        float s = 0.f, s2 = 0.f;
        for (int b = 0; b < 64; b++) { float v = sz2[b][tid]; s += v; s2 += v*v; }
        float m = s * (1.f/64.f), var = s2 * (1.f/64.f) - m*m;
        float sc = gm2[tid] * rsqrtf(var + 1e-5f);
        float sh = bem2[tid] - m*sc;
        for (int b = 0; b < 64; b++)
            sz2[b][tid] = fmaxf(fmaf(sz2[b][tid], sc, sh), 0.f);
    }
    __syncthreads();

    if (tid < 128) {
        int b = tid >> 1, c = tid & 1;
        float s = bm3[c];
#pragma unroll
        for (int j = 0; j < 64; j++) s = fmaf(sz2[b][j], Wm3[j*2 + c], s);
        out[b*2 + c] = s;
    }
}

// ---------------- launch ----------------
extern "C" void kernel_launch(void* const* d_in, const int* in_sizes, int n_in,
                              void* d_out, int out_size) {
    const float* x    = (const float*)d_in[0];
    const float* mask = (const float*)d_in[1];
    const float* W1   = (const float*)d_in[2];
    const float* b1   = (const float*)d_in[3];
    const float* g1   = (const float*)d_in[4];
    const float* be1  = (const float*)d_in[5];
    const float* W2   = (const float*)d_in[6];
    const float* b2   = (const float*)d_in[7];
    const float* g2   = (const float*)d_in[8];
    const float* be2  = (const float*)d_in[9];
    const float* Wm1  = (const float*)d_in[10];
    const float* bm1  = (const float*)d_in[11];
    const float* gm1  = (const float*)d_in[12];
    const float* bem1 = (const float*)d_in[13];
    const float* Wm2  = (const float*)d_in[14];
    const float* bm2  = (const float*)d_in[15];
    const float* gm2  = (const float*)d_in[16];
    const float* bem2 = (const float*)d_in[17];
    const float* Wm3  = (const float*)d_in[18];
    const float* bm3  = (const float*)d_in[19];
    float* out = (float*)d_out;

    static bool init = false;
    static uint32_t *pXh, *pXl, *pHbh, *pHbl, *pW1h, *pW1l, *pW2h, *pW2l;
    static float *pSum1, *pSq1, *pSum2, *pSq2;
    if (!init) {
        init = true;
        cudaFuncSetAttribute(k_simA, cudaFuncAttributeMaxDynamicSharedMemorySize, 3*SIMA_STG*4);
        cudaFuncSetAttribute(k_xw,   cudaFuncAttributeMaxDynamicSharedMemorySize, 3*GEMM_STG*4);
        cudaFuncSetAttribute(k_bmm,  cudaFuncAttributeMaxDynamicSharedMemorySize, 3*GEMM_STG*4);
        cudaFuncSetAttribute(k_mlp1, cudaFuncAttributeMaxDynamicSharedMemorySize, 3*MLP_STG*4);
        cudaGetSymbolAddress((void**)&pXh,  g_Xh);
        cudaGetSymbolAddress((void**)&pXl,  g_Xl);
        cudaGetSymbolAddress((void**)&pHbh, g_Hbh);
        cudaGetSymbolAddress((void**)&pHbl, g_Hbl);
        cudaGetSymbolAddress((void**)&pW1h, g_W1h);
        cudaGetSymbolAddress((void**)&pW1l, g_W1l);
        cudaGetSymbolAddress((void**)&pW2h, g_W2h);
        cudaGetSymbolAddress((void**)&pW2l, g_W2l);
        cudaGetSymbolAddress((void**)&pSum1, g_sum1);
        cudaGetSymbolAddress((void**)&pSq1,  g_sumsq1);
        cudaGetSymbolAddress((void**)&pSum2, g_sum2);
        cudaGetSymbolAddress((void**)&pSq2,  g_sumsq2);
    }

    // prep
    k_prep<<<NROWS/8, 256>>>(x);
    k_splitW<<<64, 256>>>(W1, W2);
    k_splitWm1<<<8192, 256>>>(Wm1);
    k_simA<<<256, 256, 3*SIMA_STG*4>>>(mask);

    // GCN layer 1
    k_xw<<<dim3(2, 256), 256, 3*GEMM_STG*4>>>(pXh, pXl, pW1h, pW1l, b1);
    k_bmm<<<dim3(2, 256), 256, 3*GEMM_STG*4>>>(pSum1, pSq1);
    k_bnsplit<<<NROWS*HH/4/256, 256>>>(pSum1, pSq1, g1, be1);

    // GCN layer 2
    k_xw<<<dim3(2, 256), 256, 3*GEMM_STG*4>>>(pHbh, pHbl, pW2h, pW2l, b2);
    k_bmm<<<dim3(2, 256), 256, 3*GEMM_STG*4>>>(pSum2, pSq2);
    k_bnsplit<<<NROWS*HH/4/256, 256>>>(pSum2, pSq2, g2, be2);

    // readout + head
    k_mlp1<<<KCHUNKS, 256, 3*MLP_STG*4>>>();
    k_red<<<32, 256>>>(bm1);
    k_head<<<1, 256>>>(gm1, bem1, Wm2, bm2, gm2, bem2, Wm3, bm3, out);
}

// round 9
// speedup vs baseline: 1.1466x; 1.0617x over previous
#include <cuda_runtime.h>
#include <cuda_bf16.h>
#include <math.h>
#include <stdint.h>

#define B     64
#define NSUB  4
#define PP    128
#define TP    512
#define DD    256
#define HH    256
#define FEAT  131072
#define M1    128
#define NROWS (B*TP)            // 32768
#define KCHUNKS 256             // split-K chunks for mlp1 (512 K each)

#define STRA  20                // A-tile row stride (16 kpair words + 4 pad)
#define STRB  136               // B-tile row stride (128 cols + 8 pad)

#define SIMA_STG   5120         // per-stage words in k_simA (A hi 2560 + A lo 2560)
#define GEMM_STG   9472         // per-stage words in k_xw/k_bmm (A 5120 + B 4352)
#define MLP_STG    6784         // per-stage words in k_mlp1 (A 2560 + Wraw 4224)
#define MLP_BS     20352        // B-split base (words) = 3*MLP_STG
#define MLP_TOT    24704        // + BH 2176 + BL 2176

// ---------------- scratch (device globals; no allocation) ----------------
__device__ float    g_invn[B*TP];
__device__ float    g_dinv[B*TP];
__device__ uint32_t g_Xh[(size_t)NROWS*128];       // x rowK split
__device__ uint32_t g_Xl[(size_t)NROWS*128];
__device__ uint32_t g_Ah[(size_t)256*PP*64];       // adjacency (raw, diag=1) kpair packed
__device__ uint32_t g_Al[(size_t)256*PP*64];
__device__ uint32_t g_W1h[128*256], g_W1l[128*256];
__device__ uint32_t g_W2h[128*256], g_W2l[128*256];
__device__ uint32_t g_XWh[(size_t)(NROWS/2)*256];  // XW*dinv+bias, kpairN packed
__device__ uint32_t g_XWl[(size_t)(NROWS/2)*256];
__device__ float    g_Hb[(size_t)NROWS*HH];        // pre-BN h (fp32)
__device__ uint32_t g_Hbh[(size_t)NROWS*128];      // post-BN h split (rowK packed)
__device__ uint32_t g_Hbl[(size_t)NROWS*128];
__device__ float    g_sum1[HH], g_sumsq1[HH], g_sum2[HH], g_sumsq2[HH];
__device__ float    g_Z1part[(size_t)KCHUNKS*B*M1];
__device__ float    g_z1[B*M1];

// ---------------- helpers ----------------
__device__ __forceinline__ void split2(float a, float b, uint32_t& h, uint32_t& l) {
    __nv_bfloat162 hb = __floats2bfloat162_rn(a, b);
    float2 hf = __bfloat1622float2(hb);
    __nv_bfloat162 lb = __floats2bfloat162_rn(a - hf.x, b - hf.y);
    h = *(uint32_t*)&hb;
    l = *(uint32_t*)&lb;
}
__device__ __forceinline__ void mma16(float* c, const uint32_t* a, const uint32_t* b) {
    asm volatile("mma.sync.aligned.m16n8k16.row.col.f32.bf16.bf16.f32 "
                 "{%0,%1,%2,%3}, {%4,%5,%6,%7}, {%8,%9}, {%0,%1,%2,%3};\n"
                 : "+f"(c[0]), "+f"(c[1]), "+f"(c[2]), "+f"(c[3])
                 : "r"(a[0]), "r"(a[1]), "r"(a[2]), "r"(a[3]),
                   "r"(b[0]), "r"(b[1]));
}
__device__ __forceinline__ void ldsm4(uint32_t* r, uint32_t addr) {
    asm volatile("ldmatrix.sync.aligned.m8n8.x4.shared.b16 {%0,%1,%2,%3}, [%4];"
                 : "=r"(r[0]), "=r"(r[1]), "=r"(r[2]), "=r"(r[3]) : "r"(addr));
}
__device__ __forceinline__ void ldsm2(uint32_t* r, uint32_t addr) {
    asm volatile("ldmatrix.sync.aligned.m8n8.x2.shared.b16 {%0,%1}, [%2];"
                 : "=r"(r[0]), "=r"(r[1]) : "r"(addr));
}
__device__ __forceinline__ void cpa(uint32_t* dst, const void* src) {
    uint32_t d = (uint32_t)__cvta_generic_to_shared(dst);
    asm volatile("cp.async.cg.shared.global [%0], [%1], 16;" :: "r"(d), "l"(src));
}
#define CP_COMMIT() asm volatile("cp.async.commit_group;")
#define CP_WAIT0()  asm volatile("cp.async.wait_group 0;")
#define CP_WAIT1()  asm volatile("cp.async.wait_group 1;")

// ---------------- prep: norms + x rowK split + BN zero; tail blocks split W1/W2 ----------------
__global__ void __launch_bounds__(256) k_prep(const float* __restrict__ x,
                                              const float* __restrict__ W1,
                                              const float* __restrict__ W2) {
    if (blockIdx.x >= NROWS/8) {
        int blk = blockIdx.x - NROWS/8;   // 0..63
        const float* W = (blk < 32) ? W1 : W2;
        uint32_t* Wh = (blk < 32) ? g_W1h : g_W2h;
        uint32_t* Wl = (blk < 32) ? g_W1l : g_W2l;
        int idx = (blk & 31) * 256 + threadIdx.x;
        int kp = idx >> 6, c = (idx & 63) * 4;
        float4 a = *(const float4*)&W[(2*kp)*256 + c];
        float4 b = *(const float4*)&W[(2*kp+1)*256 + c];
        uint4 H, L;
        split2(a.x, b.x, H.x, L.x);
        split2(a.y, b.y, H.y, L.y);
        split2(a.z, b.z, H.z, L.z);
        split2(a.w, b.w, H.w, L.w);
        *(uint4*)&Wh[kp*256 + c] = H;
        *(uint4*)&Wl[kp*256 + c] = L;
        return;
    }
    __shared__ float sX[8][260];
    int tid = threadIdx.x, w = tid >> 5, lane = tid & 31;
    if (blockIdx.x == 0) {
        g_sum1[tid] = 0.f; g_sumsq1[tid] = 0.f;
        g_sum2[tid] = 0.f; g_sumsq2[tid] = 0.f;
    }
    int row = blockIdx.x * 8 + w;
    const float* xr = x + (size_t)row * DD;
    float s = 0.f;
#pragma unroll
    for (int i = 0; i < 8; i++) {
        float v = xr[lane + 32*i];
        sX[w][lane + 32*i] = v;
        s += v*v;
    }
#pragma unroll
    for (int o = 16; o; o >>= 1) s += __shfl_xor_sync(0xffffffffu, s, o);
    if (lane == 0) g_invn[row] = 1.0f / fmaxf(sqrtf(s), 1e-12f);
    __syncthreads();
    {
        int tr = tid >> 5;
        int c0 = (tid & 31) * 8;
        uint4 H, L;
        split2(sX[tr][c0+0], sX[tr][c0+1], H.x, L.x);
        split2(sX[tr][c0+2], sX[tr][c0+3], H.y, L.y);
        split2(sX[tr][c0+4], sX[tr][c0+5], H.z, L.z);
        split2(sX[tr][c0+6], sX[tr][c0+7], H.w, L.w);
        size_t o = (size_t)(blockIdx.x*8 + tr)*128 + (c0 >> 1);
        *(uint4*)&g_Xh[o] = H;
        *(uint4*)&g_Xl[o] = L;
    }
}

// ---------------- per-(b,n): A = (cos+1)/2*mask, diag=1 -> g_Ah/l; dinv ----------------
__global__ void __launch_bounds__(256) k_simA(const float* __restrict__ mask) {
    extern __shared__ uint32_t S[];   // 3 * SIMA_STG
    __shared__ float sInv[128];
    __shared__ float sdeg[128];
    int bn = blockIdx.x;
    int rowbase = bn * 128;
    int tid = threadIdx.x, w = tid >> 5, lane = tid & 31, g = lane >> 2, t = lane & 3;
    int wm = w & 3, wn = w >> 2;
    int lrow = lane & 15, lhalf = lane >> 4;
    int blrow = lane & 7, blhalf = (lane >> 3) & 1;
    uint32_t sbase = (uint32_t)__cvta_generic_to_shared(S);
    if (tid < 128) { sInv[tid] = g_invn[rowbase + tid]; sdeg[tid] = 0.f; }

    float acc[2][8][4];
#pragma unroll
    for (int mi=0;mi<2;mi++)
#pragma unroll
        for (int ni=0;ni<8;ni++)
#pragma unroll
            for (int q=0;q<4;q++) acc[mi][ni][q] = 0.f;

#pragma unroll 1
    for (int pc = 0; pc < 2; pc++) {
        int st = (pc % 3) * SIMA_STG;
#pragma unroll
        for (int i2 = 0; i2 < 2; i2++) {
            int idx = tid + i2*256;
            int r = idx >> 2, q = (idx & 3) * 4;
            cpa(&S[st + r*STRA + q],        g_Xh + (size_t)(rowbase + r)*128 + pc*16 + q);
            cpa(&S[st + 2560 + r*STRA + q], g_Xl + (size_t)(rowbase + r)*128 + pc*16 + q);
        }
        CP_COMMIT();
    }
#pragma unroll 1
    for (int it = 0; it < 8; it++) {
        if (it < 7) { CP_WAIT1(); } else { CP_WAIT0(); }
        __syncthreads();
        if (it + 2 < 8) {
            int c = it + 2, st = (c % 3) * SIMA_STG;
#pragma unroll
            for (int i2 = 0; i2 < 2; i2++) {
                int idx = tid + i2*256;
                int r = idx >> 2, q = (idx & 3) * 4;
                cpa(&S[st + r*STRA + q],        g_Xh + (size_t)(rowbase + r)*128 + c*16 + q);
                cpa(&S[st + 2560 + r*STRA + q], g_Xl + (size_t)(rowbase + r)*128 + c*16 + q);
            }
            CP_COMMIT();
        }
        uint32_t stw = (uint32_t)((it % 3) * SIMA_STG);
#pragma unroll
        for (int kb = 0; kb < 16; kb += 8) {
            uint32_t ah[2][4], al[2][4];
#pragma unroll
            for (int mi=0;mi<2;mi++) {
                uint32_t ad = sbase + ((stw + (uint32_t)((wm*32 + mi*16 + lrow)*STRA + kb + 4*lhalf)) << 2);
                ldsm4(ah[mi], ad);
                ldsm4(al[mi], ad + (2560u << 2));
            }
#pragma unroll
            for (int ni=0;ni<8;ni++) {
                uint32_t bh[2], bl[2];
                uint32_t bd = sbase + ((stw + (uint32_t)((wn*64 + ni*8 + blrow)*STRA + kb + 4*blhalf)) << 2);
                ldsm2(bh, bd);
                ldsm2(bl, bd + (2560u << 2));
#pragma unroll
                for (int mi=0;mi<2;mi++) {
                    mma16(acc[mi][ni], ah[mi], bh);
                    mma16(acc[mi][ni], ah[mi], bl);
                    mma16(acc[mi][ni], al[mi], bh);
                }
            }
        }
    }
    __syncthreads();

#pragma unroll
    for (int ni=0;ni<8;ni++) {
        int c0 = wn*64 + ni*8 + 2*t, c1 = c0 + 1;
        int cp = c0 >> 1;
        float ic0 = sInv[c0], ic1 = sInv[c1];
#pragma unroll
        for (int mi=0;mi<2;mi++) {
            int r0 = wm*32 + mi*16 + g, r1 = r0 + 8;
            float i0 = sInv[r0], i1 = sInv[r1];
            float v00 = (r0==c0) ? 1.f : (acc[mi][ni][0]*i0*ic0 + 1.f)*0.5f*mask[r0*PP+c0];
            float v01 = (r0==c1) ? 1.f : (acc[mi][ni][1]*i0*ic1 + 1.f)*0.5f*mask[r0*PP+c1];
            float v10 = (r1==c0) ? 1.f : (acc[mi][ni][2]*i1*ic0 + 1.f)*0.5f*mask[r1*PP+c0];
            float v11 = (r1==c1) ? 1.f : (acc[mi][ni][3]*i1*ic1 + 1.f)*0.5f*mask[r1*PP+c1];
            uint32_t h, l;
            split2(v00, v01, h, l);
            g_Ah[((size_t)bn*128 + r0)*64 + cp] = h;
            g_Al[((size_t)bn*128 + r0)*64 + cp] = l;
            split2(v10, v11, h, l);
            g_Ah[((size_t)bn*128 + r1)*64 + cp] = h;
            g_Al[((size_t)bn*128 + r1)*64 + cp] = l;
            atomicAdd(&sdeg[r0], v00 + v01);
            atomicAdd(&sdeg[r1], v10 + v11);
        }
    }
    __syncthreads();
    if (tid < 128) {
        float deg = sdeg[tid];
        g_dinv[rowbase + tid] = (deg > 0.f) ? rsqrtf(fmaxf(deg, 1e-12f)) : 0.f;
    }
}

// ---------------- XW = A @ W, epilogue (acc+bias)*dinv -> g_XWh/l kpairN ----------------
__global__ void __launch_bounds__(256) k_xw(const uint32_t* __restrict__ Ah,
                                            const uint32_t* __restrict__ Al,
                                            const uint32_t* __restrict__ Wh,
                                            const uint32_t* __restrict__ Wl,
                                            const float* __restrict__ bias) {
    extern __shared__ uint32_t S[];   // 3 * GEMM_STG
    __shared__ float sDv[128];
    int tid = threadIdx.x, w = tid >> 5, lane = tid & 31, g = lane >> 2, t = lane & 3;
    int wm = w & 3, wn = w >> 2;
    int lrow = lane & 15, lhalf = lane >> 4;
    uint32_t sbase = (uint32_t)__cvta_generic_to_shared(S);
    int m0 = blockIdx.y * 128, n0 = blockIdx.x * 128;
    if (tid < 128) sDv[tid] = g_dinv[m0 + tid];

    float acc[2][8][4];
#pragma unroll
    for (int mi=0;mi<2;mi++)
#pragma unroll
        for (int ni=0;ni<8;ni++)
#pragma unroll
            for (int q=0;q<4;q++) acc[mi][ni][q] = 0.f;

#pragma unroll 1
    for (int pc = 0; pc < 2; pc++) {
        int st = (pc % 3) * GEMM_STG;
#pragma unroll
        for (int i2 = 0; i2 < 2; i2++) {
            int idx = tid + i2*256;
            int r = idx >> 2, q = (idx & 3) * 4;
            cpa(&S[st + r*STRA + q],        Ah + (size_t)(m0 + r)*128 + pc*16 + q);
            cpa(&S[st + 2560 + r*STRA + q], Al + (size_t)(m0 + r)*128 + pc*16 + q);
        }
#pragma unroll
        for (int i2 = 0; i2 < 2; i2++) {
            int idx = tid + i2*256;
            int kp = idx >> 5, cc = (idx & 31) * 4;
            cpa(&S[st + 5120 + kp*STRB + cc],        Wh + (size_t)(pc*16 + kp)*256 + n0 + cc);
            cpa(&S[st + 5120 + 2176 + kp*STRB + cc], Wl + (size_t)(pc*16 + kp)*256 + n0 + cc);
        }
        CP_COMMIT();
    }
#pragma unroll 1
    for (int it = 0; it < 8; it++) {
        if (it < 7) { CP_WAIT1(); } else { CP_WAIT0(); }
        __syncthreads();
        if (it + 2 < 8) {
            int c = it + 2, st = (c % 3) * GEMM_STG;
#pragma unroll
            for (int i2 = 0; i2 < 2; i2++) {
                int idx = tid + i2*256;
                int r = idx >> 2, q = (idx & 3) * 4;
                cpa(&S[st + r*STRA + q],        Ah + (size_t)(m0 + r)*128 + c*16 + q);
                cpa(&S[st + 2560 + r*STRA + q], Al + (size_t)(m0 + r)*128 + c*16 + q);
            }
#pragma unroll
            for (int i2 = 0; i2 < 2; i2++) {
                int idx = tid + i2*256;
                int kp = idx >> 5, cc = (idx & 31) * 4;
                cpa(&S[st + 5120 + kp*STRB + cc],        Wh + (size_t)(c*16 + kp)*256 + n0 + cc);
                cpa(&S[st + 5120 + 2176 + kp*STRB + cc], Wl + (size_t)(c*16 + kp)*256 + n0 + cc);
            }
            CP_COMMIT();
        }
        uint32_t stw = (uint32_t)((it % 3) * GEMM_STG);
        const uint32_t* BH = S + (it % 3) * GEMM_STG + 5120;
        const uint32_t* BL = BH + 2176;
#pragma unroll
        for (int kb = 0; kb < 16; kb += 8) {
            uint32_t ah[2][4], al[2][4];
#pragma unroll
            for (int mi=0;mi<2;mi++) {
                uint32_t ad = sbase + ((stw + (uint32_t)((wm*32 + mi*16 + lrow)*STRA + kb + 4*lhalf)) << 2);
                ldsm4(ah[mi], ad);
                ldsm4(al[mi], ad + (2560u << 2));
            }
#pragma unroll
            for (int ni=0;ni<8;ni++) {
                int cb = wn*64 + ni*8 + g;
                uint32_t bh[2], bl[2];
                bh[0] = BH[(kb+t  )*STRB + cb]; bl[0] = BL[(kb+t  )*STRB + cb];
                bh[1] = BH[(kb+t+4)*STRB + cb]; bl[1] = BL[(kb+t+4)*STRB + cb];
#pragma unroll
                for (int mi=0;mi<2;mi++) {
                    mma16(acc[mi][ni], ah[mi], bh);
                    mma16(acc[mi][ni], ah[mi], bl);
                    mma16(acc[mi][ni], al[mi], bh);
                }
            }
        }
    }
    // epilogue: (acc + bias) * dinv -> smem staging -> packed kpairN global
    __syncthreads();
    float* stg = (float*)S;   // 128 x 132 floats = 16896 words
#pragma unroll
    for (int mi=0;mi<2;mi++) {
        int r0 = wm*32 + mi*16 + g, r1 = r0 + 8;
        float d0 = sDv[r0], d1 = sDv[r1];
#pragma unroll
        for (int ni=0;ni<8;ni++) {
            int c0 = wn*64 + ni*8 + 2*t;
            float b0 = bias[n0 + c0], b1 = bias[n0 + c0 + 1];
            *(float2*)&stg[r0*132 + c0] = make_float2((acc[mi][ni][0]+b0)*d0, (acc[mi][ni][1]+b1)*d0);
            *(float2*)&stg[r1*132 + c0] = make_float2((acc[mi][ni][2]+b0)*d1, (acc[mi][ni][3]+b1)*d1);
        }
    }
    __syncthreads();
#pragma unroll
    for (int i2 = 0; i2 < 8; i2++) {
        int idx = tid + i2*256;
        int kp = idx >> 5, c = (idx & 31) * 4;
        float4 u = *(float4*)&stg[(2*kp  )*132 + c];
        float4 v = *(float4*)&stg[(2*kp+1)*132 + c];
        uint4 H, L;
        split2(u.x, v.x, H.x, L.x);
        split2(u.y, v.y, H.y, L.y);
        split2(u.z, v.z, H.z, L.z);
        split2(u.w, v.w, H.w, L.w);
        *(uint4*)&g_XWh[((size_t)(m0>>1) + kp)*256 + n0 + c] = H;
        *(uint4*)&g_XWl[((size_t)(m0>>1) + kp)*256 + n0 + c] = L;
    }
}

// ---------------- H = dinv_i * A(bn) @ XWs + fused BN stats -> g_Hb ----------------
__global__ void __launch_bounds__(256) k_bmm(float* __restrict__ sumArr,
                                             float* __restrict__ sqArr) {
    extern __shared__ uint32_t S[];   // 3 * GEMM_STG
    __shared__ float sDv[128];
    __shared__ float sSum[128], sSq[128];
    int bn = blockIdx.y;
    int h0 = blockIdx.x * 128;
    int rowbase = bn * 128;
    int tid = threadIdx.x, w = tid >> 5, lane = tid & 31, g = lane >> 2, t = lane & 3;
    int wm = w & 3, wn = w >> 2;
    int lrow = lane & 15, lhalf = lane >> 4;
    uint32_t sbase = (uint32_t)__cvta_generic_to_shared(S);
    if (tid < 128) { sDv[tid] = g_dinv[rowbase + tid]; sSum[tid] = 0.f; sSq[tid] = 0.f; }

    float acc[2][8][4];
#pragma unroll
    for (int mi=0;mi<2;mi++)
#pragma unroll
        for (int ni=0;ni<8;ni++)
#pragma unroll
            for (int q=0;q<4;q++) acc[mi][ni][q] = 0.f;

#pragma unroll 1
    for (int pc = 0; pc < 2; pc++) {
        int st = (pc % 3) * GEMM_STG;
#pragma unroll
        for (int i2 = 0; i2 < 2; i2++) {
            int idx = tid + i2*256;
            int r = idx >> 2, q = (idx & 3) * 4;
            cpa(&S[st + r*STRA + q],        g_Ah + ((size_t)bn*128 + r)*64 + pc*16 + q);
            cpa(&S[st + 2560 + r*STRA + q], g_Al + ((size_t)bn*128 + r)*64 + pc*16 + q);
        }
#pragma unroll
        for (int i2 = 0; i2 < 2; i2++) {
            int idx = tid + i2*256;
            int kp = idx >> 5, cc = (idx & 31) * 4;
            cpa(&S[st + 5120 + kp*STRB + cc],        g_XWh + ((size_t)(bn*64) + pc*16 + kp)*256 + h0 + cc);
            cpa(&S[st + 5120 + 2176 + kp*STRB + cc], g_XWl + ((size_t)(bn*64) + pc*16 + kp)*256 + h0 + cc);
        }
        CP_COMMIT();
    }
#pragma unroll 1
    for (int it = 0; it < 4; it++) {
        if (it < 3) { CP_WAIT1(); } else { CP_WAIT0(); }
        __syncthreads();
        if (it + 2 < 4) {
            int c = it + 2, st = (c % 3) * GEMM_STG;
#pragma unroll
            for (int i2 = 0; i2 < 2; i2++) {
                int idx = tid + i2*256;
                int r = idx >> 2, q = (idx & 3) * 4;
                cpa(&S[st + r*STRA + q],        g_Ah + ((size_t)bn*128 + r)*64 + c*16 + q);
                cpa(&S[st + 2560 + r*STRA + q], g_Al + ((size_t)bn*128 + r)*64 + c*16 + q);
            }
#pragma unroll
            for (int i2 = 0; i2 < 2; i2++) {
                int idx = tid + i2*256;
                int kp = idx >> 5, cc = (idx & 31) * 4;
                cpa(&S[st + 5120 + kp*STRB + cc],        g_XWh + ((size_t)(bn*64) + c*16 + kp)*256 + h0 + cc);
                cpa(&S[st + 5120 + 2176 + kp*STRB + cc], g_XWl + ((size_t)(bn*64) + c*16 + kp)*256 + h0 + cc);
            }
            CP_COMMIT();
        }
        uint32_t stw = (uint32_t)((it % 3) * GEMM_STG);
        const uint32_t* BH = S + (it % 3) * GEMM_STG + 5120;
        const uint32_t* BL = BH + 2176;
#pragma unroll
        for (int kb = 0; kb < 16; kb += 8) {
            uint32_t ah[2][4], al[2][4];
#pragma unroll
            for (int mi=0;mi<2;mi++) {
                uint32_t ad = sbase + ((stw + (uint32_t)((wm*32 + mi*16 + lrow)*STRA + kb + 4*lhalf)) << 2);
                ldsm4(ah[mi], ad);
                ldsm4(al[mi], ad + (2560u << 2));
            }
#pragma unroll
            for (int ni=0;ni<8;ni++) {
                int cb = wn*64 + ni*8 + g;
                uint32_t bh[2], bl[2];
                bh[0] = BH[(kb+t  )*STRB + cb]; bl[0] = BL[(kb+t  )*STRB + cb];
                bh[1] = BH[(kb+t+4)*STRB + cb]; bl[1] = BL[(kb+t+4)*STRB + cb];
#pragma unroll
                for (int mi=0;mi<2;mi++) {
                    mma16(acc[mi][ni], ah[mi], bh);
                    mma16(acc[mi][ni], ah[mi], bl);
                    mma16(acc[mi][ni], al[mi], bh);
                }
            }
        }
    }
    float* base = g_Hb + (size_t)rowbase * HH;
#pragma unroll
    for (int ni=0;ni<8;ni++) {
        int cl = wn*64 + ni*8 + 2*t;
        float cs0 = 0.f, cs1 = 0.f, cq0 = 0.f, cq1 = 0.f;
#pragma unroll
        for (int mi=0;mi<2;mi++) {
            int r0 = wm*32 + mi*16 + g, r1 = r0 + 8;
            float d0 = sDv[r0], d1 = sDv[r1];
            float v00 = acc[mi][ni][0]*d0, v01 = acc[mi][ni][1]*d0;
            float v10 = acc[mi][ni][2]*d1, v11 = acc[mi][ni][3]*d1;
            *(float2*)&base[(size_t)r0*HH + h0 + cl] = make_float2(v00, v01);
            *(float2*)&base[(size_t)r1*HH + h0 + cl] = make_float2(v10, v11);
            cs0 += v00 + v10; cs1 += v01 + v11;
            cq0 += v00*v00 + v10*v10; cq1 += v01*v01 + v11*v11;
        }
        atomicAdd(&sSum[cl],   cs0);
        atomicAdd(&sSum[cl+1], cs1);
        atomicAdd(&sSq[cl],    cq0);
        atomicAdd(&sSq[cl+1],  cq1);
    }
    __syncthreads();
    if (tid < 128) {
        atomicAdd(&sumArr[h0 + tid], sSum[tid]);
        atomicAdd(&sqArr[h0 + tid],  sSq[tid]);
    }
}

// ---------------- bnsplit (finalize folded): g_Hb -> g_Hbh/l (rowK) ----------------
__global__ void __launch_bounds__(256) k_bnsplit(const float* __restrict__ sumArr,
                                                 const float* __restrict__ sqArr,
                                                 const float* __restrict__ gam,
                                                 const float* __restrict__ bet) {
    __shared__ float sSc[256], sSh[256];
    {
        int c = threadIdx.x;
        const float invn = 1.0f / (float)NROWS;
        float m = sumArr[c] * invn;
        float v = sqArr[c] * invn - m*m;
        float sc = gam[c] * rsqrtf(v + 1e-5f);
        sSc[c] = sc; sSh[c] = bet[c] - m*sc;
    }
    __syncthreads();
    size_t i4 = (size_t)blockIdx.x * 256 + threadIdx.x;
    float4 v = ((const float4*)g_Hb)[i4];
    int c = (int)((i4 * 4) & 255);
    v.x = fmaxf(fmaf(v.x, sSc[c],   sSh[c]),   0.f);
    v.y = fmaxf(fmaf(v.y, sSc[c+1], sSh[c+1]), 0.f);
    v.z = fmaxf(fmaf(v.z, sSc[c+2], sSh[c+2]), 0.f);
    v.w = fmaxf(fmaf(v.w, sSc[c+3], sSh[c+3]), 0.f);
    uint32_t h0, l0, h1, l1;
    split2(v.x, v.y, h0, l0);
    split2(v.z, v.w, h1, l1);
    ((uint2*)g_Hbh)[i4] = make_uint2(h0, h1);
    ((uint2*)g_Hbl)[i4] = make_uint2(l0, l1);
}

// ---------------- split-K readout GEMM (in-kernel Wm1 split, 3-stage) ----------------
__global__ void __launch_bounds__(256) k_mlp1(const float* __restrict__ Wm1) {
    extern __shared__ uint32_t S[];   // MLP_TOT words
    int kc0 = blockIdx.x;             // 0..255
    int kbase = kc0 * 512;            // fp32 k-row base
    size_t kwb = (size_t)kc0 * 256;   // word base into FEAT/2
    int tid = threadIdx.x, w = tid >> 5, lane = tid & 31, g = lane >> 2, t = lane & 3;
    int wm = w & 3, wn = w >> 2;
    int lrow = lane & 15, lhalf = lane >> 4;
    uint32_t sbase = (uint32_t)__cvta_generic_to_shared(S);
    uint32_t* BHs = S + MLP_BS;
    uint32_t* BLs = S + MLP_BS + 2176;
    float acc[8][4];
#pragma unroll
    for (int ni=0;ni<8;ni++)
#pragma unroll
        for (int q=0;q<4;q++) acc[ni][q] = 0.f;

#pragma unroll 1
    for (int pc = 0; pc < 2; pc++) {
        int st = (pc % 3) * MLP_STG;
        {
            int r = tid >> 2, q = (tid & 3) * 4;
            cpa(&S[st + r*STRA + q],        g_Hbh + (size_t)r*(FEAT/2) + kwb + pc*16 + q);
            cpa(&S[st + 1280 + r*STRA + q], g_Hbl + (size_t)r*(FEAT/2) + kwb + pc*16 + q);
        }
#pragma unroll
        for (int i2 = 0; i2 < 4; i2++) {
            int idx = tid + i2*256;
            int rr = idx >> 5, cc = (idx & 31) * 4;
            cpa(&S[st + 2560 + rr*132 + cc], Wm1 + (size_t)(kbase + pc*32 + rr)*128 + cc);
        }
        CP_COMMIT();
    }
#pragma unroll 1
    for (int it = 0; it < 16; it++) {
        if (it < 15) { CP_WAIT1(); } else { CP_WAIT0(); }
        __syncthreads();
        if (it + 2 < 16) {
            int c = it + 2, st = (c % 3) * MLP_STG;
            {
                int r = tid >> 2, q = (tid & 3) * 4;
                cpa(&S[st + r*STRA + q],        g_Hbh + (size_t)r*(FEAT/2) + kwb + c*16 + q);
                cpa(&S[st + 1280 + r*STRA + q], g_Hbl + (size_t)r*(FEAT/2) + kwb + c*16 + q);
            }
#pragma unroll
            for (int i2 = 0; i2 < 4; i2++) {
                int idx = tid + i2*256;
                int rr = idx >> 5, cc = (idx & 31) * 4;
                cpa(&S[st + 2560 + rr*132 + cc], Wm1 + (size_t)(kbase + c*32 + rr)*128 + cc);
            }
            CP_COMMIT();
        }
        // split raw Wm1 of chunk it -> BHs/BLs
        {
            const float* raw = (const float*)(S + (it % 3) * MLP_STG + 2560);
#pragma unroll
            for (int i2 = 0; i2 < 2; i2++) {
                int idx = tid + i2*256;
                int kp = idx >> 5, cc = (idx & 31) * 4;
                float4 u = *(const float4*)&raw[(2*kp  )*132 + cc];
                float4 v = *(const float4*)&raw[(2*kp+1)*132 + cc];
                uint4 H, L;
                split2(u.x, v.x, H.x, L.x);
                split2(u.y, v.y, H.y, L.y);
                split2(u.z, v.z, H.z, L.z);
                split2(u.w, v.w, H.w, L.w);
                *(uint4*)&BHs[kp*STRB + cc] = H;
                *(uint4*)&BLs[kp*STRB + cc] = L;
            }
        }
        __syncthreads();
        uint32_t stw = (uint32_t)((it % 3) * MLP_STG);
#pragma unroll
        for (int kb = 0; kb < 16; kb += 8) {
            uint32_t ah[4], al[4];
            uint32_t ad = sbase + ((stw + (uint32_t)((wm*16 + lrow)*STRA + kb + 4*lhalf)) << 2);
            ldsm4(ah, ad);
            ldsm4(al, ad + (1280u << 2));
#pragma unroll
            for (int ni=0;ni<8;ni++) {
                int cb = wn*64 + ni*8 + g;
                uint32_t bh[2], bl[2];
                bh[0] = BHs[(kb+t  )*STRB + cb]; bl[0] = BLs[(kb+t  )*STRB + cb];
                bh[1] = BHs[(kb+t+4)*STRB + cb]; bl[1] = BLs[(kb+t+4)*STRB + cb];
                mma16(acc[ni], ah, bh);
                mma16(acc[ni], ah, bl);
                mma16(acc[ni], al, bh);
            }
        }
    }
    float* out = g_Z1part + (size_t)kc0 * (B*M1);
    int r0 = wm*16 + g, r1 = r0 + 8;
#pragma unroll
    for (int ni=0;ni<8;ni++) {
        int c0 = wn*64 + ni*8 + 2*t;
        *(float2*)&out[r0*M1 + c0] = make_float2(acc[ni][0], acc[ni][1]);
        *(float2*)&out[r1*M1 + c0] = make_float2(acc[ni][2], acc[ni][3]);
    }
}

__global__ void k_red(const float* __restrict__ bm1) {
    int o = blockIdx.x*256 + threadIdx.x;   // 0..8191
    float s = bm1[o & 127];
    for (int kc = 0; kc < KCHUNKS; kc++) s += g_Z1part[(size_t)kc*(B*M1) + o];
    g_z1[o] = s;
}

// ---------------- head (exact fp32) ----------------
__global__ void __launch_bounds__(256) k_head(const float* __restrict__ gm1, const float* __restrict__ bem1,
                                              const float* __restrict__ Wm2, const float* __restrict__ bm2,
                                              const float* __restrict__ gm2, const float* __restrict__ bem2,
                                              const float* __restrict__ Wm3, const float* __restrict__ bm3,
                                              float* __restrict__ out) {
    __shared__ float sz1[64][128];
    __shared__ float sz2[64][64];
    int tid = threadIdx.x;

    if (tid < 128) {
        float s = 0.f, s2 = 0.f;
        for (int b = 0; b < 64; b++) { float v = g_z1[b*128 + tid]; s += v; s2 += v*v; }
        float m = s * (1.f/64.f), var = s2 * (1.f/64.f) - m*m;
        float sc = gm1[tid] * rsqrtf(var + 1e-5f);
        float sh = bem1[tid] - m*sc;
        for (int b = 0; b < 64; b++)
            sz1[b][tid] = fmaxf(fmaf(g_z1[b*128 + tid], sc, sh), 0.f);
    }
    __syncthreads();

    for (int o = tid; o < 4096; o += 256) {
        int b = o >> 6, j = o & 63;
        float s = bm2[j];
#pragma unroll 8
        for (int m = 0; m < 128; m++) s = fmaf(sz1[b][m], Wm2[m*64 + j], s);
        sz2[b][j] = s;
    }
    __syncthreads();

    if (tid < 64) {
        float s = 0.f, s2 = 0.f;
        for (int b = 0; b < 64; b++) { float v = sz2[b][tid]; s += v; s2 += v*v; }
        float m = s * (1.f/64.f), var = s2 * (1.f/64.f) - m*m;
        float sc = gm2[tid] * rsqrtf(var + 1e-5f);
        float sh = bem2[tid] - m*sc;
        for (int b = 0; b < 64; b++)
            sz2[b][tid] = fmaxf(fmaf(sz2[b][tid], sc, sh), 0.f);
    }
    __syncthreads();

    if (tid < 128) {
        int b = tid >> 1, c = tid & 1;
        float s = bm3[c];
#pragma unroll
        for (int j = 0; j < 64; j++) s = fmaf(sz2[b][j], Wm3[j*2 + c], s);
        out[b*2 + c] = s;
    }
}

// ---------------- launch ----------------
extern "C" void kernel_launch(void* const* d_in, const int* in_sizes, int n_in,
                              void* d_out, int out_size) {
    const float* x    = (const float*)d_in[0];
    const float* mask = (const float*)d_in[1];
    const float* W1   = (const float*)d_in[2];
    const float* b1   = (const float*)d_in[3];
    const float* g1   = (const float*)d_in[4];
    const float* be1  = (const float*)d_in[5];
    const float* W2   = (const float*)d_in[6];
    const float* b2   = (const float*)d_in[7];
    const float* g2   = (const float*)d_in[8];
    const float* be2  = (const float*)d_in[9];
    const float* Wm1  = (const float*)d_in[10];
    const float* bm1  = (const float*)d_in[11];
    const float* gm1  = (const float*)d_in[12];
    const float* bem1 = (const float*)d_in[13];
    const float* Wm2  = (const float*)d_in[14];
    const float* bm2  = (const float*)d_in[15];
    const float* gm2  = (const float*)d_in[16];
    const float* bem2 = (const float*)d_in[17];
    const float* Wm3  = (const float*)d_in[18];
    const float* bm3  = (const float*)d_in[19];
    float* out = (float*)d_out;

    static bool init = false;
    static uint32_t *pXh, *pXl, *pHbh, *pHbl, *pW1h, *pW1l, *pW2h, *pW2l;
    static float *pSum1, *pSq1, *pSum2, *pSq2;
    if (!init) {
        init = true;
        cudaFuncSetAttribute(k_simA, cudaFuncAttributeMaxDynamicSharedMemorySize, 3*SIMA_STG*4);
        cudaFuncSetAttribute(k_xw,   cudaFuncAttributeMaxDynamicSharedMemorySize, 3*GEMM_STG*4);
        cudaFuncSetAttribute(k_bmm,  cudaFuncAttributeMaxDynamicSharedMemorySize, 3*GEMM_STG*4);
        cudaFuncSetAttribute(k_mlp1, cudaFuncAttributeMaxDynamicSharedMemorySize, MLP_TOT*4);
        cudaGetSymbolAddress((void**)&pXh,  g_Xh);
        cudaGetSymbolAddress((void**)&pXl,  g_Xl);
        cudaGetSymbolAddress((void**)&pHbh, g_Hbh);
        cudaGetSymbolAddress((void**)&pHbl, g_Hbl);
        cudaGetSymbolAddress((void**)&pW1h, g_W1h);
        cudaGetSymbolAddress((void**)&pW1l, g_W1l);
        cudaGetSymbolAddress((void**)&pW2h, g_W2h);
        cudaGetSymbolAddress((void**)&pW2l, g_W2l);
        cudaGetSymbolAddress((void**)&pSum1, g_sum1);
        cudaGetSymbolAddress((void**)&pSq1,  g_sumsq1);
        cudaGetSymbolAddress((void**)&pSum2, g_sum2);
        cudaGetSymbolAddress((void**)&pSq2,  g_sumsq2);
    }

    // prep (norms + x split + BN zero + W1/W2 split in tail blocks)
    k_prep<<<NROWS/8 + 64, 256>>>(x, W1, W2);
    k_simA<<<256, 256, 3*SIMA_STG*4>>>(mask);

    // GCN layer 1
    k_xw<<<dim3(2, 256), 256, 3*GEMM_STG*4>>>(pXh, pXl, pW1h, pW1l, b1);
    k_bmm<<<dim3(2, 256), 256, 3*GEMM_STG*4>>>(pSum1, pSq1);
    k_bnsplit<<<NROWS*HH/4/256, 256>>>(pSum1, pSq1, g1, be1);

    // GCN layer 2
    k_xw<<<dim3(2, 256), 256, 3*GEMM_STG*4>>>(pHbh, pHbl, pW2h, pW2l, b2);
    k_bmm<<<dim3(2, 256), 256, 3*GEMM_STG*4>>>(pSum2, pSq2);
    k_bnsplit<<<NROWS*HH/4/256, 256>>>(pSum2, pSq2, g2, be2);

    // readout + head
    k_mlp1<<<KCHUNKS, 256, MLP_TOT*4>>>(Wm1);
    k_red<<<32, 256>>>(bm1);
    k_head<<<1, 256>>>(gm1, bem1, Wm2, bm2, gm2, bem2, Wm3, bm3, out);
}